// round 1
// baseline (speedup 1.0000x reference)
#include <cuda_runtime.h>
#include <cuda_fp16.h>
#include <cstdint>

#define HH 96
#define WW 96
#define CC 21
#define NN 9216          // HH*WW
#define CP 24            // padded channel count for mma tiles (3 x n8)

// ---------------- scratch (device globals; no allocation allowed) ----------------
__device__ __half g_K[(size_t)NN * NN];   // bilateral kernel matrix, fp16, ~170MB
__device__ __half g_pT[CP * NN];          // softmax probs, transposed [c][n], fp16
__device__ float  g_p32[NN * CC];         // softmax probs fp32 (spatial path)
__device__ float  g_tmp[NN * CC];         // separable conv intermediate
__device__ float  g_S[NN * CC];           // spatial message
__device__ float  g_B[NN * CP];           // bilateral message (padded)
__device__ float  g_q[NN * CC];           // current q
__device__ float  g_G[HH * HH];           // 1D spatial gaussian table G[a][b]
__device__ float  g_Ws[CC * CC];          // compat[k][c] * ws[c]
__device__ float  g_Wb[CC * CC];          // compat[k][c] * wb[c]
__device__ float  g_col[NN * 3];          // colors * 8 (= /theta_beta)

// ---------------- prep: color features, gaussian table, folded weights ----------------
__global__ void prep_kernel(const float* __restrict__ ref, const float* __restrict__ ws,
                            const float* __restrict__ wb, const float* __restrict__ cm) {
    int t = blockIdx.x * 256 + threadIdx.x;
    if (t < NN) {
        g_col[t * 3 + 0] = ref[t * 3 + 0] * 8.0f;
        g_col[t * 3 + 1] = ref[t * 3 + 1] * 8.0f;
        g_col[t * 3 + 2] = ref[t * 3 + 2] * 8.0f;
    }
    if (t < HH * HH) {
        int a = t / HH, b = t % HH;
        float d = (float)(a - b);
        g_G[t] = __expf(-0.5f * d * d / 9.0f);   // theta_gamma = 3
    }
    if (t < CC * CC) {
        g_Ws[t] = cm[t] * ws[t % CC];
        g_Wb[t] = cm[t] * wb[t % CC];
    }
}

// ---------------- build bilateral kernel matrix (once per launch) ----------------
__global__ void build_k_kernel() {
    int j  = blockIdx.x * 256 + threadIdx.x;   // column index
    int i0 = blockIdx.y * 16;                  // row tile
    float yj = (float)(j / WW), xj = (float)(j % WW);
    float rj = g_col[j * 3 + 0], gj = g_col[j * 3 + 1], bj = g_col[j * 3 + 2];
#pragma unroll 4
    for (int t = 0; t < 16; t++) {
        int i = i0 + t;
        float yi = (float)(i / WW), xi = (float)(i % WW);
        float dy = yi - yj, dx = xi - xj;
        float dp = (dy * dy + dx * dx) * (1.0f / 64.0f);   // theta_alpha = 8
        float dr = rj - g_col[i * 3 + 0];
        float dg = gj - g_col[i * 3 + 1];
        float db = bj - g_col[i * 3 + 2];
        float d2 = dp + dr * dr + dg * dg + db * db;
        g_K[(size_t)i * NN + j] = __float2half_rn(__expf(-0.5f * d2));
    }
}

// ---------------- softmax over channels; emits fp32 [n][c] and fp16 transposed [c][n] ----------------
__global__ void softmax_kernel(const float* __restrict__ u, int first) {
    int n = blockIdx.x * 256 + threadIdx.x;
    if (n >= NN) return;
    const float* src = first ? (u + n * CC) : (g_q + n * CC);
    float v[CC];
    float mx = -1e30f;
#pragma unroll
    for (int c = 0; c < CC; c++) { v[c] = src[c]; mx = fmaxf(mx, v[c]); }
    float s = 0.0f;
#pragma unroll
    for (int c = 0; c < CC; c++) { v[c] = __expf(v[c] - mx); s += v[c]; }
    float inv = 1.0f / s;
#pragma unroll
    for (int c = 0; c < CC; c++) {
        float p = v[c] * inv;
        g_p32[n * CC + c] = p;
        g_pT[c * NN + n]  = __float2half_rn(p);
    }
#pragma unroll
    for (int c = CC; c < CP; c++) g_pT[c * NN + n] = __float2half_rn(0.0f);
}

// ---------------- separable spatial filtering (exact) ----------------
__global__ void conv_x_kernel() {   // grid = HH (one row y per block), block = 512
    __shared__ float s[WW * CC];    // 8064 B
    int y = blockIdx.x;
    const float* row = g_p32 + y * WW * CC;
    for (int t = threadIdx.x; t < WW * CC; t += blockDim.x) s[t] = row[t];
    __syncthreads();
    for (int idx = threadIdx.x; idx < WW * CC; idx += blockDim.x) {
        int x = idx / CC, c = idx - x * CC;
        const float* Gr = g_G + x * WW;
        float acc = 0.0f;
#pragma unroll 8
        for (int xp = 0; xp < WW; xp++) acc += Gr[xp] * s[xp * CC + c];
        g_tmp[y * WW * CC + idx] = acc;
    }
}

__global__ void conv_y_kernel() {   // grid = HH (output row y per block), block = 512
    __shared__ float gsh[HH];
    int y = blockIdx.x;
    if (threadIdx.x < HH) gsh[threadIdx.x] = g_G[y * HH + threadIdx.x];
    __syncthreads();
    for (int xc = threadIdx.x; xc < WW * CC; xc += blockDim.x) {
        float acc = 0.0f;
#pragma unroll 8
        for (int yp = 0; yp < HH; yp++) acc += gsh[yp] * g_tmp[yp * WW * CC + xc];
        g_S[y * WW * CC + xc] = acc;
    }
}

// ---------------- bilateral GEMM: Bout[N x 24] = K[N x N] @ p[N x 24] via mma.sync fp16 ----------------
__device__ __forceinline__ void mma16816(float* d, uint32_t a0, uint32_t a1, uint32_t a2,
                                         uint32_t a3, uint32_t b0, uint32_t b1) {
    asm volatile(
        "mma.sync.aligned.m16n8k16.row.col.f32.f16.f16.f32 "
        "{%0,%1,%2,%3},{%4,%5,%6,%7},{%8,%9},{%0,%1,%2,%3};\n"
        : "+f"(d[0]), "+f"(d[1]), "+f"(d[2]), "+f"(d[3])
        : "r"(a0), "r"(a1), "r"(a2), "r"(a3), "r"(b0), "r"(b1));
}

__global__ void gemm_kernel() {     // grid = 144, block = 128 (4 warps, each: 16 rows x 24 cols)
    int warp = threadIdx.x >> 5, lane = threadIdx.x & 31;
    int grp = lane >> 2, tig = lane & 3;
    int row0 = blockIdx.x * 64 + warp * 16 + grp;
    const __half* a0p = g_K + (size_t)row0 * NN + 2 * tig;
    const __half* a1p = a0p + (size_t)8 * NN;
    const __half* b0p = g_pT + (size_t)grp * NN + 2 * tig;
    float d[3][4];
#pragma unroll
    for (int i = 0; i < 3; i++)
#pragma unroll
        for (int j = 0; j < 4; j++) d[i][j] = 0.0f;

#pragma unroll 4
    for (int k = 0; k < NN; k += 16) {
        uint32_t a0 = *reinterpret_cast<const uint32_t*>(a0p + k);
        uint32_t a2 = *reinterpret_cast<const uint32_t*>(a0p + k + 8);
        uint32_t a1 = *reinterpret_cast<const uint32_t*>(a1p + k);
        uint32_t a3 = *reinterpret_cast<const uint32_t*>(a1p + k + 8);
#pragma unroll
        for (int nt = 0; nt < 3; nt++) {
            uint32_t b0 = *reinterpret_cast<const uint32_t*>(b0p + (size_t)nt * 8 * NN + k);
            uint32_t b1 = *reinterpret_cast<const uint32_t*>(b0p + (size_t)nt * 8 * NN + k + 8);
            mma16816(d[nt], a0, a1, a2, a3, b0, b1);
        }
    }
#pragma unroll
    for (int nt = 0; nt < 3; nt++) {
        int col = nt * 8 + 2 * tig;
        *reinterpret_cast<float2*>(&g_B[(size_t)row0 * CP + col]) =
            make_float2(d[nt][0], d[nt][1]);
        *reinterpret_cast<float2*>(&g_B[(size_t)(row0 + 8) * CP + col]) =
            make_float2(d[nt][2], d[nt][3]);
    }
}

// ---------------- update: q = u - S@Ws^T - B@Wb^T ----------------
__global__ void update_kernel(const float* __restrict__ u, float* __restrict__ outp, int last) {
    __shared__ float sws[CC * CC], swb[CC * CC];
    for (int t = threadIdx.x; t < CC * CC; t += 256) { sws[t] = g_Ws[t]; swb[t] = g_Wb[t]; }
    __syncthreads();
    int n = blockIdx.x * 256 + threadIdx.x;
    if (n >= NN) return;
    float sv[CC], bv[CC];
#pragma unroll
    for (int c = 0; c < CC; c++) { sv[c] = g_S[n * CC + c]; bv[c] = g_B[n * CP + c]; }
    float* dst = (last ? outp : g_q) + n * CC;
    const float* un = u + n * CC;
#pragma unroll
    for (int k = 0; k < CC; k++) {
        float acc = 0.0f;
#pragma unroll
        for (int c = 0; c < CC; c++)
            acc += sws[k * CC + c] * sv[c] + swb[k * CC + c] * bv[c];
        dst[k] = un[k] - acc;
    }
}

// ---------------- launch ----------------
extern "C" void kernel_launch(void* const* d_in, const int* in_sizes, int n_in,
                              void* d_out, int out_size) {
    const float* u   = (const float*)d_in[0];
    const float* ref = (const float*)d_in[1];
    const float* ws  = (const float*)d_in[2];
    const float* wb  = (const float*)d_in[3];
    const float* cm  = (const float*)d_in[4];
    float* out = (float*)d_out;

    prep_kernel<<<36, 256>>>(ref, ws, wb, cm);
    build_k_kernel<<<dim3(36, 576), 256>>>();

    for (int it = 0; it < 5; it++) {
        softmax_kernel<<<36, 256>>>(u, it == 0 ? 1 : 0);
        conv_x_kernel<<<HH, 512>>>();
        conv_y_kernel<<<HH, 512>>>();
        gemm_kernel<<<144, 128>>>();
        update_kernel<<<36, 256>>>(u, out, it == 4 ? 1 : 0);
    }
}

// round 2
// speedup vs baseline: 4.1276x; 4.1276x over previous
#include <cuda_runtime.h>
#include <cuda_fp16.h>
#include <cstdint>

#define HH 96
#define WW 96
#define CC 21
#define NN 9216          // HH*WW
#define CP 24            // padded channel count for mma tiles (3 x n8)

#define KT 64            // k-tile (halves)
#define RB 64            // rows per gemm block
#define ASTR 72          // smem row stride in halves (144B; pad kills bank conflicts)
#define KSPLIT 2
#define KHALF (NN / KSPLIT)   // 4608
#define NSTAGE (KHALF / KT)   // 72

// ---------------- scratch (device globals; no allocation allowed) ----------------
__device__ __half g_K[(size_t)NN * NN];   // bilateral kernel matrix, fp16, ~170MB
__device__ __half g_pT[CP * NN];          // softmax probs, transposed [c][n], fp16
__device__ float  g_p32[NN * CC];         // softmax probs fp32 (spatial path)
__device__ float  g_tmp[NN * CC];         // separable conv intermediate
__device__ float  g_S[NN * CC];           // spatial message
__device__ float  g_B[NN * CP];           // bilateral message, k-split half 0
__device__ float  g_B2[NN * CP];          // bilateral message, k-split half 1
__device__ float  g_q[NN * CC];           // current q
__device__ float  g_G[HH * HH];           // 1D spatial gaussian table G[a][b]
__device__ float  g_Ws[CC * CC];          // compat[k][c] * ws[c]
__device__ float  g_Wb[CC * CC];          // compat[k][c] * wb[c]
__device__ float  g_col[NN * 3];          // colors * 8 (= /theta_beta)

// ---------------- cp.async helpers ----------------
#define CP_ASYNC16(dst, src) \
    asm volatile("cp.async.cg.shared.global [%0], [%1], 16;\n" :: "r"(dst), "l"(src))
#define CP_COMMIT() asm volatile("cp.async.commit_group;\n" ::: "memory")
#define CP_WAIT1()  asm volatile("cp.async.wait_group 1;\n" ::: "memory")

// ---------------- prep: color features, gaussian table, folded weights ----------------
__global__ void prep_kernel(const float* __restrict__ ref, const float* __restrict__ ws,
                            const float* __restrict__ wb, const float* __restrict__ cm) {
    int t = blockIdx.x * 256 + threadIdx.x;
    if (t < NN) {
        g_col[t * 3 + 0] = ref[t * 3 + 0] * 8.0f;
        g_col[t * 3 + 1] = ref[t * 3 + 1] * 8.0f;
        g_col[t * 3 + 2] = ref[t * 3 + 2] * 8.0f;
    }
    if (t < HH * HH) {
        int a = t / HH, b = t % HH;
        float d = (float)(a - b);
        g_G[t] = __expf(-0.5f * d * d / 9.0f);   // theta_gamma = 3
    }
    if (t < CC * CC) {
        g_Ws[t] = cm[t] * ws[t % CC];
        g_Wb[t] = cm[t] * wb[t % CC];
    }
}

// ---------------- build bilateral kernel matrix (once per launch) ----------------
__global__ void build_k_kernel() {
    int j  = blockIdx.x * 256 + threadIdx.x;   // column index
    int i0 = blockIdx.y * 16;                  // row tile
    float yj = (float)(j / WW), xj = (float)(j % WW);
    float rj = g_col[j * 3 + 0], gj = g_col[j * 3 + 1], bj = g_col[j * 3 + 2];
#pragma unroll 4
    for (int t = 0; t < 16; t++) {
        int i = i0 + t;
        float yi = (float)(i / WW), xi = (float)(i % WW);
        float dy = yi - yj, dx = xi - xj;
        float dp = (dy * dy + dx * dx) * (1.0f / 64.0f);   // theta_alpha = 8
        float dr = rj - g_col[i * 3 + 0];
        float dg = gj - g_col[i * 3 + 1];
        float db = bj - g_col[i * 3 + 2];
        float d2 = dp + dr * dr + dg * dg + db * db;
        g_K[(size_t)i * NN + j] = __float2half_rn(__expf(-0.5f * d2));
    }
}

// ---------------- softmax; fp32 [n][c] and coalesced fp16 transposed [c][n] ----------------
__global__ void softmax_kernel(const float* __restrict__ u, int first) {
    __shared__ __half sp[CP][264];             // padded transpose buffer
    int tid = threadIdx.x;
    int n = blockIdx.x * 256 + tid;
    const float* src = first ? (u + n * CC) : (g_q + n * CC);
    float v[CC];
    float mx = -1e30f;
#pragma unroll
    for (int c = 0; c < CC; c++) { v[c] = src[c]; mx = fmaxf(mx, v[c]); }
    float s = 0.0f;
#pragma unroll
    for (int c = 0; c < CC; c++) { v[c] = __expf(v[c] - mx); s += v[c]; }
    float inv = 1.0f / s;
#pragma unroll
    for (int c = 0; c < CC; c++) {
        float p = v[c] * inv;
        g_p32[n * CC + c] = p;
        sp[c][tid] = __float2half_rn(p);
    }
#pragma unroll
    for (int c = CC; c < CP; c++) sp[c][tid] = __float2half_rn(0.0f);
    __syncthreads();
    int base = blockIdx.x * 256;
#pragma unroll
    for (int c = 0; c < CP; c++) g_pT[c * NN + base + tid] = sp[c][tid];
}

// ---------------- separable spatial filtering (exact) ----------------
__global__ void conv_x_kernel() {   // grid = (96, 4), block = 256
    __shared__ float s[WW * CC];    // 8064 B : one image row of probs
    int y = blockIdx.x;
    const float* row = g_p32 + y * WW * CC;
    for (int t = threadIdx.x; t < WW * CC; t += 256) s[t] = row[t];
    __syncthreads();
    int idx = blockIdx.y * 504 + threadIdx.x;
    for (int r = 0; r < 2; r++, idx += 256) {
        if (idx >= (blockIdx.y + 1) * 504 || idx >= WW * CC) continue;
        int x = idx / CC, c = idx - x * CC;
        const float* Gr = g_G + x * WW;
        float a0 = 0.f, a1 = 0.f, a2 = 0.f, a3 = 0.f;
#pragma unroll
        for (int xp = 0; xp < WW; xp += 4) {
            a0 += Gr[xp + 0] * s[(xp + 0) * CC + c];
            a1 += Gr[xp + 1] * s[(xp + 1) * CC + c];
            a2 += Gr[xp + 2] * s[(xp + 2) * CC + c];
            a3 += Gr[xp + 3] * s[(xp + 3) * CC + c];
        }
        g_tmp[y * WW * CC + idx] = (a0 + a1) + (a2 + a3);
    }
}

__global__ void conv_y_kernel() {   // grid = (96, 4), block = 256
    __shared__ float gsh[HH];
    int y = blockIdx.x;
    if (threadIdx.x < HH) gsh[threadIdx.x] = g_G[y * HH + threadIdx.x];
    __syncthreads();
    int idx = blockIdx.y * 504 + threadIdx.x;
    for (int r = 0; r < 2; r++, idx += 256) {
        if (idx >= (blockIdx.y + 1) * 504 || idx >= WW * CC) continue;
        float a0 = 0.f, a1 = 0.f, a2 = 0.f, a3 = 0.f;
#pragma unroll
        for (int yp = 0; yp < HH; yp += 4) {
            a0 += gsh[yp + 0] * g_tmp[(yp + 0) * WW * CC + idx];
            a1 += gsh[yp + 1] * g_tmp[(yp + 1) * WW * CC + idx];
            a2 += gsh[yp + 2] * g_tmp[(yp + 2) * WW * CC + idx];
            a3 += gsh[yp + 3] * g_tmp[(yp + 3) * WW * CC + idx];
        }
        g_S[y * WW * CC + idx] = (a0 + a1) + (a2 + a3);
    }
}

// ---------------- bilateral GEMM: B[N x 24] = K[N x N] @ pT^T, cp.async pipelined ----------------
__device__ __forceinline__ void mma16816(float* d, uint32_t a0, uint32_t a1, uint32_t a2,
                                         uint32_t a3, uint32_t b0, uint32_t b1) {
    asm volatile(
        "mma.sync.aligned.m16n8k16.row.col.f32.f16.f16.f32 "
        "{%0,%1,%2,%3},{%4,%5,%6,%7},{%8,%9},{%0,%1,%2,%3};\n"
        : "+f"(d[0]), "+f"(d[1]), "+f"(d[2]), "+f"(d[3])
        : "r"(a0), "r"(a1), "r"(a2), "r"(a3), "r"(b0), "r"(b1));
}

__global__ void __launch_bounds__(128, 2) gemm_kernel() {
    // grid = (144, 2), block = 128 (4 warps). Each block: 64 rows, half the K range.
    __shared__ __half sA[3][RB * ASTR];   // 27648 B
    __shared__ __half sB[3][CP * ASTR];   // 10368 B
    int tid = threadIdx.x;
    int warp = tid >> 5, lane = tid & 31;
    int grp = lane >> 2, tig = lane & 3;
    int rowBase = blockIdx.x * RB;
    int kh = blockIdx.y;
    size_t kb0 = (size_t)kh * KHALF;

    uint32_t sA_u = (uint32_t)__cvta_generic_to_shared(&sA[0][0]);
    uint32_t sB_u = (uint32_t)__cvta_generic_to_shared(&sB[0][0]);

    auto prefetch = [&](int s, int buf) {
        size_t kbase = kb0 + (size_t)s * KT;
#pragma unroll
        for (int i = 0; i < 4; i++) {            // 512 chunks of 16B for A
            int chunk = tid + i * 128;
            int r = chunk >> 3, c = chunk & 7;
            const __half* src = g_K + (size_t)(rowBase + r) * NN + kbase + c * 8;
            uint32_t dst = sA_u + (uint32_t)(buf * RB * ASTR + r * ASTR + c * 8) * 2;
            CP_ASYNC16(dst, src);
        }
#pragma unroll
        for (int i = 0; i < 2; i++) {            // 192 chunks for B tile
            int chunk = tid + i * 128;
            if (chunk < CP * 8) {
                int r = chunk >> 3, c = chunk & 7;
                const __half* src = g_pT + (size_t)r * NN + kbase + c * 8;
                uint32_t dst = sB_u + (uint32_t)(buf * CP * ASTR + r * ASTR + c * 8) * 2;
                CP_ASYNC16(dst, src);
            }
        }
    };

    float d[3][4];
#pragma unroll
    for (int i = 0; i < 3; i++)
#pragma unroll
        for (int j = 0; j < 4; j++) d[i][j] = 0.0f;

    prefetch(0, 0); CP_COMMIT();
    prefetch(1, 1); CP_COMMIT();

    int arow0 = (warp * 16 + grp) * ASTR;
    int arow1 = arow0 + 8 * ASTR;

    for (int s = 0; s < NSTAGE; s++) {
        CP_WAIT1();
        __syncthreads();
        if (s + 2 < NSTAGE) prefetch(s + 2, (s + 2) % 3);
        CP_COMMIT();
        const __half* A = sA[s % 3];
        const __half* Bm = sB[s % 3];
#pragma unroll
        for (int kk = 0; kk < 4; kk++) {
            int ko = kk * 16 + 2 * tig;
            uint32_t a0 = *reinterpret_cast<const uint32_t*>(A + arow0 + ko);
            uint32_t a1 = *reinterpret_cast<const uint32_t*>(A + arow1 + ko);
            uint32_t a2 = *reinterpret_cast<const uint32_t*>(A + arow0 + ko + 8);
            uint32_t a3 = *reinterpret_cast<const uint32_t*>(A + arow1 + ko + 8);
#pragma unroll
            for (int nt = 0; nt < 3; nt++) {
                uint32_t b0 = *reinterpret_cast<const uint32_t*>(Bm + (grp + nt * 8) * ASTR + ko);
                uint32_t b1 = *reinterpret_cast<const uint32_t*>(Bm + (grp + nt * 8) * ASTR + ko + 8);
                mma16816(d[nt], a0, a1, a2, a3, b0, b1);
            }
        }
    }

    float* outp = kh ? g_B2 : g_B;
    int row0 = rowBase + warp * 16 + grp;
#pragma unroll
    for (int nt = 0; nt < 3; nt++) {
        int col = nt * 8 + 2 * tig;
        *reinterpret_cast<float2*>(&outp[(size_t)row0 * CP + col]) =
            make_float2(d[nt][0], d[nt][1]);
        *reinterpret_cast<float2*>(&outp[(size_t)(row0 + 8) * CP + col]) =
            make_float2(d[nt][2], d[nt][3]);
    }
}

// ---------------- update: q = u - S@Ws^T - (B+B2)@Wb^T ----------------
__global__ void update_kernel(const float* __restrict__ u, float* __restrict__ outp, int last) {
    __shared__ float sws[CC * CC], swb[CC * CC];
    for (int t = threadIdx.x; t < CC * CC; t += 256) { sws[t] = g_Ws[t]; swb[t] = g_Wb[t]; }
    __syncthreads();
    int n = blockIdx.x * 256 + threadIdx.x;
    if (n >= NN) return;
    float sv[CC], bv[CC];
#pragma unroll
    for (int c = 0; c < CC; c++) {
        sv[c] = g_S[n * CC + c];
        bv[c] = g_B[n * CP + c] + g_B2[n * CP + c];
    }
    float* dst = (last ? outp : g_q) + n * CC;
    const float* un = u + n * CC;
#pragma unroll
    for (int k = 0; k < CC; k++) {
        float acc = 0.0f;
#pragma unroll
        for (int c = 0; c < CC; c++)
            acc += sws[k * CC + c] * sv[c] + swb[k * CC + c] * bv[c];
        dst[k] = un[k] - acc;
    }
}

// ---------------- launch ----------------
extern "C" void kernel_launch(void* const* d_in, const int* in_sizes, int n_in,
                              void* d_out, int out_size) {
    const float* u   = (const float*)d_in[0];
    const float* ref = (const float*)d_in[1];
    const float* ws  = (const float*)d_in[2];
    const float* wb  = (const float*)d_in[3];
    const float* cm  = (const float*)d_in[4];
    float* out = (float*)d_out;

    prep_kernel<<<36, 256>>>(ref, ws, wb, cm);
    build_k_kernel<<<dim3(36, 576), 256>>>();

    for (int it = 0; it < 5; it++) {
        softmax_kernel<<<36, 256>>>(u, it == 0 ? 1 : 0);
        conv_x_kernel<<<dim3(96, 4), 256>>>();
        conv_y_kernel<<<dim3(96, 4), 256>>>();
        gemm_kernel<<<dim3(144, 2), 128>>>();
        update_kernel<<<36, 256>>>(u, out, it == 4 ? 1 : 0);
    }
}

// round 3
// speedup vs baseline: 4.1614x; 1.0082x over previous
#include <cuda_runtime.h>
#include <cuda_fp16.h>
#include <cstdint>

#define HH 96
#define WW 96
#define CC 21
#define NN 9216          // HH*WW
#define CP 24            // padded channel count for mma tiles (3 x n8)

#define KT 64            // k-tile (halves)
#define RB 64            // rows per gemm block
#define ASTR 72          // smem row stride in halves (144B; pad kills bank conflicts)
#define KSPLIT 4
#define KQ (NN / KSPLIT)      // 2304
#define NSTAGE (KQ / KT)      // 36

// ---------------- scratch (device globals; no allocation allowed) ----------------
__device__ __half g_K[(size_t)NN * NN];   // bilateral kernel matrix, fp16, ~170MB
__device__ __half g_pT[CP * NN];          // softmax probs, planar [c][n], fp16
__device__ float  g_tmp[CC * NN];         // separable conv intermediate, planar [c][n]
__device__ float  g_S[CC * NN];           // spatial message, planar [c][n]
__device__ float  g_B[NN * CP];           // bilateral partial, k-split 0
__device__ float  g_B2[NN * CP];          // bilateral partial, k-split 1
__device__ float  g_B3[NN * CP];          // bilateral partial, k-split 2
__device__ float  g_B4[NN * CP];          // bilateral partial, k-split 3
__device__ float  g_q[NN * CC];           // current q, [n][c]
__device__ float  g_G[HH * HH];           // 1D spatial gaussian table G[a][b]
__device__ float  g_Ws[CC * CC];          // compat[k][c] * ws[c]
__device__ float  g_Wb[CC * CC];          // compat[k][c] * wb[c]
__device__ float  g_col[NN * 3];          // colors * 8 (= /theta_beta)

// ---------------- cp.async helpers ----------------
#define CP_ASYNC16(dst, src) \
    asm volatile("cp.async.cg.shared.global [%0], [%1], 16;\n" :: "r"(dst), "l"(src))
#define CP_COMMIT() asm volatile("cp.async.commit_group;\n" ::: "memory")
#define CP_WAIT1()  asm volatile("cp.async.wait_group 1;\n" ::: "memory")

// ---------------- prep: color features, gaussian table, folded weights ----------------
__global__ void prep_kernel(const float* __restrict__ ref, const float* __restrict__ ws,
                            const float* __restrict__ wb, const float* __restrict__ cm) {
    int t = blockIdx.x * 256 + threadIdx.x;
    if (t < NN) {
        g_col[t * 3 + 0] = ref[t * 3 + 0] * 8.0f;
        g_col[t * 3 + 1] = ref[t * 3 + 1] * 8.0f;
        g_col[t * 3 + 2] = ref[t * 3 + 2] * 8.0f;
    }
    if (t < HH * HH) {
        int a = t / HH, b = t % HH;
        float d = (float)(a - b);
        g_G[t] = __expf(-0.5f * d * d / 9.0f);   // theta_gamma = 3
    }
    if (t < CC * CC) {
        g_Ws[t] = cm[t] * ws[t % CC];
        g_Wb[t] = cm[t] * wb[t % CC];
    }
}

// ---------------- build bilateral kernel matrix (once per launch) ----------------
__global__ void build_k_kernel() {
    int j2 = blockIdx.x * 128 + threadIdx.x;   // pair of columns
    int j0 = j2 * 2;
    int i0 = blockIdx.y * 16;                  // row tile
    float yj = (float)(j0 / WW), xj0 = (float)(j0 % WW), xj1 = xj0 + 1.0f;
    float yj1 = yj;
    if (j0 % WW == WW - 1) { xj1 = 0.0f; yj1 = yj + 1.0f; }  // wrap (j0+1 next row)
    float r0 = g_col[j0 * 3 + 0], gg0 = g_col[j0 * 3 + 1], b0 = g_col[j0 * 3 + 2];
    float r1 = g_col[j0 * 3 + 3], gg1 = g_col[j0 * 3 + 4], b1 = g_col[j0 * 3 + 5];
#pragma unroll 4
    for (int t = 0; t < 16; t++) {
        int i = i0 + t;
        float yi = (float)(i / WW), xi = (float)(i % WW);
        float ri = g_col[i * 3 + 0], gi = g_col[i * 3 + 1], bi = g_col[i * 3 + 2];
        float dy0 = yi - yj,  dx0 = xi - xj0;
        float dy1 = yi - yj1, dx1 = xi - xj1;
        float d20 = (dy0 * dy0 + dx0 * dx0) * (1.0f / 64.0f);
        float d21 = (dy1 * dy1 + dx1 * dx1) * (1.0f / 64.0f);
        float dr0 = ri - r0, dg0 = gi - gg0, db0 = bi - b0;
        float dr1 = ri - r1, dg1 = gi - gg1, db1 = bi - b1;
        d20 += dr0 * dr0 + dg0 * dg0 + db0 * db0;
        d21 += dr1 * dr1 + dg1 * dg1 + db1 * db1;
        __half2 hv = __floats2half2_rn(__expf(-0.5f * d20), __expf(-0.5f * d21));
        *reinterpret_cast<__half2*>(&g_K[(size_t)i * NN + j0]) = hv;
    }
}

// ---------------- softmax; emits coalesced fp16 planar [c][n] ----------------
__global__ void softmax_kernel(const float* __restrict__ u, int first) {
    __shared__ __half sp[CP][264];             // padded transpose buffer
    int tid = threadIdx.x;
    int n = blockIdx.x * 256 + tid;
    const float* src = first ? (u + n * CC) : (g_q + n * CC);
    float v[CC];
    float mx = -1e30f;
#pragma unroll
    for (int c = 0; c < CC; c++) { v[c] = src[c]; mx = fmaxf(mx, v[c]); }
    float s = 0.0f;
#pragma unroll
    for (int c = 0; c < CC; c++) { v[c] = __expf(v[c] - mx); s += v[c]; }
    float inv = 1.0f / s;
#pragma unroll
    for (int c = 0; c < CC; c++) sp[c][tid] = __float2half_rn(v[c] * inv);
#pragma unroll
    for (int c = CC; c < CP; c++) sp[c][tid] = __float2half_rn(0.0f);
    __syncthreads();
    int base = blockIdx.x * 256;
#pragma unroll
    for (int c = 0; c < CP; c++) g_pT[c * NN + base + tid] = sp[c][tid];
}

// ---------------- separable spatial filtering (exact math, planar layout) ----------------
__global__ void conv_x_kernel() {   // grid = (96 y, 21 c), block = 96 (thread = x)
    __shared__ float s[WW];
    int y = blockIdx.x, c = blockIdx.y;
    int x = threadIdx.x;
    s[x] = __half2float(g_pT[c * NN + y * WW + x]);
    __syncthreads();
    const float4* Gr = reinterpret_cast<const float4*>(g_G + x * WW);
    const float4* s4 = reinterpret_cast<const float4*>(s);
    float a0 = 0.f, a1 = 0.f, a2 = 0.f, a3 = 0.f;
#pragma unroll
    for (int q = 0; q < WW / 4; q++) {
        float4 g = Gr[q];
        float4 p = s4[q];
        a0 += g.x * p.x; a1 += g.y * p.y; a2 += g.z * p.z; a3 += g.w * p.w;
    }
    g_tmp[c * NN + y * WW + x] = (a0 + a1) + (a2 + a3);
}

__global__ void conv_y_kernel() {   // grid = (12 ytile, 21 c), block = 96 (thread = x)
    __shared__ float gs[8][HH];
    int c = blockIdx.y, y0 = blockIdx.x * 8, x = threadIdx.x;
    for (int t = threadIdx.x; t < 8 * HH; t += 96)
        gs[t / HH][t % HH] = g_G[(y0 + t / HH) * HH + (t % HH)];
    __syncthreads();
    float acc[8];
#pragma unroll
    for (int i = 0; i < 8; i++) acc[i] = 0.0f;
    const float* tp = g_tmp + c * NN + x;
#pragma unroll 4
    for (int yp = 0; yp < HH; yp++) {
        float v = tp[yp * WW];
#pragma unroll
        for (int i = 0; i < 8; i++) acc[i] += gs[i][yp] * v;
    }
#pragma unroll
    for (int i = 0; i < 8; i++)
        g_S[c * NN + (y0 + i) * WW + x] = acc[i];
}

// ---------------- bilateral GEMM: B[N x 24] = K[N x N] @ pT^T, cp.async pipelined ----------------
__device__ __forceinline__ void mma16816(float* d, uint32_t a0, uint32_t a1, uint32_t a2,
                                         uint32_t a3, uint32_t b0, uint32_t b1) {
    asm volatile(
        "mma.sync.aligned.m16n8k16.row.col.f32.f16.f16.f32 "
        "{%0,%1,%2,%3},{%4,%5,%6,%7},{%8,%9},{%0,%1,%2,%3};\n"
        : "+f"(d[0]), "+f"(d[1]), "+f"(d[2]), "+f"(d[3])
        : "r"(a0), "r"(a1), "r"(a2), "r"(a3), "r"(b0), "r"(b1));
}

__global__ void __launch_bounds__(128, 4) gemm_kernel() {
    // grid = (144, 4), block = 128 (4 warps). Each block: 64 rows, quarter K range.
    __shared__ __half sA[3][RB * ASTR];   // 27648 B
    __shared__ __half sB[3][CP * ASTR];   // 10368 B
    int tid = threadIdx.x;
    int warp = tid >> 5, lane = tid & 31;
    int grp = lane >> 2, tig = lane & 3;
    int rowBase = blockIdx.x * RB;
    int kh = blockIdx.y;
    size_t kb0 = (size_t)kh * KQ;

    uint32_t sA_u = (uint32_t)__cvta_generic_to_shared(&sA[0][0]);
    uint32_t sB_u = (uint32_t)__cvta_generic_to_shared(&sB[0][0]);

    auto prefetch = [&](int s, int buf) {
        size_t kbase = kb0 + (size_t)s * KT;
#pragma unroll
        for (int i = 0; i < 4; i++) {            // 512 chunks of 16B for A
            int chunk = tid + i * 128;
            int r = chunk >> 3, c = chunk & 7;
            const __half* src = g_K + (size_t)(rowBase + r) * NN + kbase + c * 8;
            uint32_t dst = sA_u + (uint32_t)(buf * RB * ASTR + r * ASTR + c * 8) * 2;
            CP_ASYNC16(dst, src);
        }
#pragma unroll
        for (int i = 0; i < 2; i++) {            // 192 chunks for B tile
            int chunk = tid + i * 128;
            if (chunk < CP * 8) {
                int r = chunk >> 3, c = chunk & 7;
                const __half* src = g_pT + (size_t)r * NN + kbase + c * 8;
                uint32_t dst = sB_u + (uint32_t)(buf * CP * ASTR + r * ASTR + c * 8) * 2;
                CP_ASYNC16(dst, src);
            }
        }
    };

    float d[3][4];
#pragma unroll
    for (int i = 0; i < 3; i++)
#pragma unroll
        for (int j = 0; j < 4; j++) d[i][j] = 0.0f;

    prefetch(0, 0); CP_COMMIT();
    prefetch(1, 1); CP_COMMIT();

    int arow0 = (warp * 16 + grp) * ASTR;
    int arow1 = arow0 + 8 * ASTR;

    for (int s = 0; s < NSTAGE; s++) {
        CP_WAIT1();
        __syncthreads();
        if (s + 2 < NSTAGE) prefetch(s + 2, (s + 2) % 3);
        CP_COMMIT();
        const __half* A = sA[s % 3];
        const __half* Bm = sB[s % 3];
#pragma unroll
        for (int kk = 0; kk < 4; kk++) {
            int ko = kk * 16 + 2 * tig;
            uint32_t a0 = *reinterpret_cast<const uint32_t*>(A + arow0 + ko);
            uint32_t a1 = *reinterpret_cast<const uint32_t*>(A + arow1 + ko);
            uint32_t a2 = *reinterpret_cast<const uint32_t*>(A + arow0 + ko + 8);
            uint32_t a3 = *reinterpret_cast<const uint32_t*>(A + arow1 + ko + 8);
#pragma unroll
            for (int nt = 0; nt < 3; nt++) {
                uint32_t b0 = *reinterpret_cast<const uint32_t*>(Bm + (grp + nt * 8) * ASTR + ko);
                uint32_t b1 = *reinterpret_cast<const uint32_t*>(Bm + (grp + nt * 8) * ASTR + ko + 8);
                mma16816(d[nt], a0, a1, a2, a3, b0, b1);
            }
        }
    }

    float* outp = (kh == 0) ? g_B : (kh == 1) ? g_B2 : (kh == 2) ? g_B3 : g_B4;
    int row0 = rowBase + warp * 16 + grp;
#pragma unroll
    for (int nt = 0; nt < 3; nt++) {
        int col = nt * 8 + 2 * tig;
        *reinterpret_cast<float2*>(&outp[(size_t)row0 * CP + col]) =
            make_float2(d[nt][0], d[nt][1]);
        *reinterpret_cast<float2*>(&outp[(size_t)(row0 + 8) * CP + col]) =
            make_float2(d[nt][2], d[nt][3]);
    }
}

// ---------------- update: q = u - S@Ws^T - (B+B2+B3+B4)@Wb^T ----------------
__global__ void update_kernel(const float* __restrict__ u, float* __restrict__ outp, int last) {
    __shared__ float sws[CC * CC], swb[CC * CC];
    for (int t = threadIdx.x; t < CC * CC; t += 256) { sws[t] = g_Ws[t]; swb[t] = g_Wb[t]; }
    __syncthreads();
    int n = blockIdx.x * 256 + threadIdx.x;
    if (n >= NN) return;
    float sv[CC], bv[CC];
#pragma unroll
    for (int c = 0; c < CC; c++) {
        sv[c] = g_S[c * NN + n];
        bv[c] = g_B[n * CP + c] + g_B2[n * CP + c] + g_B3[n * CP + c] + g_B4[n * CP + c];
    }
    float* dst = (last ? outp : g_q) + n * CC;
    const float* un = u + n * CC;
#pragma unroll
    for (int k = 0; k < CC; k++) {
        float acc = 0.0f;
#pragma unroll
        for (int c = 0; c < CC; c++)
            acc += sws[k * CC + c] * sv[c] + swb[k * CC + c] * bv[c];
        dst[k] = un[k] - acc;
    }
}

// ---------------- launch ----------------
extern "C" void kernel_launch(void* const* d_in, const int* in_sizes, int n_in,
                              void* d_out, int out_size) {
    const float* u   = (const float*)d_in[0];
    const float* ref = (const float*)d_in[1];
    const float* ws  = (const float*)d_in[2];
    const float* wb  = (const float*)d_in[3];
    const float* cm  = (const float*)d_in[4];
    float* out = (float*)d_out;

    prep_kernel<<<36, 256>>>(ref, ws, wb, cm);
    build_k_kernel<<<dim3(36, 576), 128>>>();

    for (int it = 0; it < 5; it++) {
        softmax_kernel<<<36, 256>>>(u, it == 0 ? 1 : 0);
        conv_x_kernel<<<dim3(96, 21), 96>>>();
        conv_y_kernel<<<dim3(12, 21), 96>>>();
        gemm_kernel<<<dim3(144, 4), 128>>>();
        update_kernel<<<36, 256>>>(u, out, it == 4 ? 1 : 0);
    }
}

// round 4
// speedup vs baseline: 5.2167x; 1.2536x over previous
#include <cuda_runtime.h>
#include <cuda_fp16.h>
#include <cuda_fp8.h>
#include <cstdint>

#define HH 96
#define WW 96
#define CC 21
#define NN 9216          // HH*WW
#define CP 24            // padded channel count
#define BROWS 48         // B operand rows: 24 hi + 24 lo (residual)

#define KT 128           // k-tile (fp8 elements = bytes)
#define RB 64            // rows per gemm block
#define KSPLIT 4
#define KQ (NN / KSPLIT)      // 2304
#define NSTAGE (KQ / KT)      // 18
#define SA_BUF (RB * 128)     // 8192 B per stage
#define SB_BUF (BROWS * 128)  // 6144 B per stage

// ---------------- scratch (device globals; no allocation allowed) ----------------
__device__ uint8_t g_K8[(size_t)NN * NN];   // bilateral kernel, e4m3, ~85MB
__device__ __half  g_pT[CC * NN];           // probs planar [c][n], fp16 (conv path)
__device__ uint8_t g_pT8[BROWS * NN];       // probs e4m3 planar: rows 0-23 hi, 24-47 lo*64
__device__ float   g_tmp[CC * NN];          // conv intermediate, planar
__device__ float   g_S[CC * NN];            // spatial message, planar
__device__ float   g_Bp[KSPLIT][NN * CP];   // bilateral partials per k-split
__device__ float   g_G[HH * HH];            // 1D spatial gaussian G[a][b]
__device__ float   g_Ws[CC * CC];           // compat[k][c] * ws[c]
__device__ float   g_Wb[CC * CC];           // compat[k][c] * wb[c]
__device__ float   g_col[NN * 3];           // colors * 8 (= /theta_beta)

// ---------------- cp.async helpers ----------------
#define CP_ASYNC16(dst, src) \
    asm volatile("cp.async.cg.shared.global [%0], [%1], 16;\n" :: "r"(dst), "l"(src))
#define CP_COMMIT() asm volatile("cp.async.commit_group;\n" ::: "memory")
#define CP_WAIT1()  asm volatile("cp.async.wait_group 1;\n" ::: "memory")

__device__ __forceinline__ uint8_t to_e4m3(float f) {
    return (uint8_t)__nv_cvt_float_to_fp8(f, __NV_SATFINITE, __NV_E4M3);
}
__device__ __forceinline__ float from_e4m3(uint8_t s) {
    return __half2float(__nv_cvt_fp8_to_halfraw((__nv_fp8_storage_t)s, __NV_E4M3));
}

// ---------------- prep ----------------
__global__ void prep_kernel(const float* __restrict__ ref, const float* __restrict__ ws,
                            const float* __restrict__ wb, const float* __restrict__ cm) {
    int t = blockIdx.x * 256 + threadIdx.x;
    if (t < NN) {
        g_col[t * 3 + 0] = ref[t * 3 + 0] * 8.0f;
        g_col[t * 3 + 1] = ref[t * 3 + 1] * 8.0f;
        g_col[t * 3 + 2] = ref[t * 3 + 2] * 8.0f;
    }
    if (t < HH * HH) {
        int a = t / HH, b = t % HH;
        float d = (float)(a - b);
        g_G[t] = __expf(-0.5f * d * d / 9.0f);   // theta_gamma = 3
    }
    if (t < CC * CC) {
        g_Ws[t] = cm[t] * ws[t % CC];
        g_Wb[t] = cm[t] * wb[t % CC];
    }
}

// ---------------- build bilateral kernel matrix (fp8, once) ----------------
__global__ void build_k_kernel() {
    int jq = blockIdx.x * 128 + threadIdx.x;   // quad of columns
    int j0 = jq * 4;
    int i0 = blockIdx.y * 16;
    float yj = (float)(j0 / WW), xj = (float)(j0 % WW);  // quad within one row
    float cr[4], cg[4], cb[4];
#pragma unroll
    for (int t = 0; t < 4; t++) {
        cr[t] = g_col[(j0 + t) * 3 + 0];
        cg[t] = g_col[(j0 + t) * 3 + 1];
        cb[t] = g_col[(j0 + t) * 3 + 2];
    }
#pragma unroll 4
    for (int t = 0; t < 16; t++) {
        int i = i0 + t;
        float yi = (float)(i / WW), xi = (float)(i % WW);
        float ri = g_col[i * 3 + 0], gi = g_col[i * 3 + 1], bi = g_col[i * 3 + 2];
        float dy = yi - yj;
        uint32_t packed = 0;
#pragma unroll
        for (int s = 0; s < 4; s++) {
            float dx = xi - (xj + (float)s);
            float d2 = (dy * dy + dx * dx) * (1.0f / 64.0f);
            float dr = ri - cr[s], dg = gi - cg[s], db = bi - cb[s];
            d2 += dr * dr + dg * dg + db * db;
            packed |= (uint32_t)to_e4m3(__expf(-0.5f * d2)) << (8 * s);
        }
        *reinterpret_cast<uint32_t*>(&g_K8[(size_t)i * NN + j0]) = packed;
    }
}

// ---------------- prob emission (shared by softmax0 and update) ----------------
__device__ __forceinline__ void emit_probs(const float* v, int n) {
    // v = logits[CC]; writes fp16 planar + fp8 hi/lo planar at pixel n
    float mx = -1e30f;
#pragma unroll
    for (int c = 0; c < CC; c++) mx = fmaxf(mx, v[c]);
    float s = 0.0f;
    float e[CC];
#pragma unroll
    for (int c = 0; c < CC; c++) { e[c] = __expf(v[c] - mx); s += e[c]; }
    float inv = 1.0f / s;
#pragma unroll
    for (int c = 0; c < CC; c++) {
        float p = e[c] * inv;
        g_pT[c * NN + n] = __float2half_rn(p);
        uint8_t hi = to_e4m3(p);
        float res = 64.0f * (p - from_e4m3(hi));
        g_pT8[c * NN + n] = hi;
        g_pT8[(CP + c) * NN + n] = to_e4m3(res);
    }
#pragma unroll
    for (int c = CC; c < CP; c++) {
        g_pT8[c * NN + n] = 0;
        g_pT8[(CP + c) * NN + n] = 0;
    }
}

__global__ void softmax0_kernel(const float* __restrict__ u) {
    int n = blockIdx.x * 256 + threadIdx.x;
    float v[CC];
#pragma unroll
    for (int c = 0; c < CC; c++) v[c] = u[n * CC + c];
    emit_probs(v, n);
}

// ---------------- separable spatial filtering (exact) ----------------
__global__ void conv_x_kernel() {   // grid = 96 (y), block = 288 (x + 96*cg), cg: 7 ch each
    __shared__ float sp[CC * WW];   // probs row [c][x]
    int y = blockIdx.x;
    int tid = threadIdx.x;
    for (int t = tid; t < CC * WW; t += 288)
        sp[t] = __half2float(g_pT[(t / WW) * NN + y * WW + (t % WW)]);
    __syncthreads();
    int x = tid % 96, cg = tid / 96;
    int c0 = cg * 7;
    float acc[7];
#pragma unroll
    for (int i = 0; i < 7; i++) acc[i] = 0.0f;
#pragma unroll 4
    for (int xp = 0; xp < WW; xp++) {
        float g = g_G[xp * WW + x];    // coalesced across x, L1-hot
#pragma unroll
        for (int i = 0; i < 7; i++) acc[i] += g * sp[(c0 + i) * WW + xp];
    }
#pragma unroll
    for (int i = 0; i < 7; i++)
        g_tmp[(c0 + i) * NN + y * WW + x] = acc[i];
}

__global__ void conv_y_kernel() {   // grid = (12 ytile, 21 c), block = 96 (x)
    __shared__ float gsh[8][HH];
    int c = blockIdx.y, y0 = blockIdx.x * 8, x = threadIdx.x;
    for (int t = threadIdx.x; t < 8 * HH; t += 96)
        gsh[t / HH][t % HH] = g_G[(y0 + t / HH) * HH + (t % HH)];
    __syncthreads();
    float acc[8];
#pragma unroll
    for (int i = 0; i < 8; i++) acc[i] = 0.0f;
    const float* tp = g_tmp + c * NN + x;
#pragma unroll 4
    for (int yp = 0; yp < HH; yp++) {
        float v = tp[yp * WW];
#pragma unroll
        for (int i = 0; i < 8; i++) acc[i] += gsh[i][yp] * v;
    }
#pragma unroll
    for (int i = 0; i < 8; i++)
        g_S[c * NN + (y0 + i) * WW + x] = acc[i];
}

// ---------------- fp8 GEMM: Bp = K8[N x N] @ pT8^T (hi & lo), cp.async pipelined ----------------
__device__ __forceinline__ void mma_fp8(float* d, uint32_t a0, uint32_t a1, uint32_t a2,
                                        uint32_t a3, uint32_t b0, uint32_t b1) {
    asm volatile(
        "mma.sync.aligned.m16n8k32.row.col.f32.e4m3.e4m3.f32 "
        "{%0,%1,%2,%3},{%4,%5,%6,%7},{%8,%9},{%0,%1,%2,%3};\n"
        : "+f"(d[0]), "+f"(d[1]), "+f"(d[2]), "+f"(d[3])
        : "r"(a0), "r"(a1), "r"(a2), "r"(a3), "r"(b0), "r"(b1));
}

__global__ void __launch_bounds__(128, 4) gemm_kernel() {
    // grid = (144, KSPLIT), block = 128 (4 warps). Block: 64 rows, quarter K range.
    __shared__ __align__(16) uint8_t sA[3 * SA_BUF];   // 24576 B
    __shared__ __align__(16) uint8_t sB[3 * SB_BUF];   // 18432 B
    int tid = threadIdx.x;
    int warp = tid >> 5, lane = tid & 31;
    int grp = lane >> 2, tig = lane & 3;
    int rowBase = blockIdx.x * RB;
    size_t kb0 = (size_t)blockIdx.y * KQ;

    uint32_t sA_u = (uint32_t)__cvta_generic_to_shared(&sA[0]);
    uint32_t sB_u = (uint32_t)__cvta_generic_to_shared(&sB[0]);

    auto prefetch = [&](int s, int buf) {
        size_t kbase = kb0 + (size_t)s * KT;
#pragma unroll
        for (int i = 0; i < 4; i++) {            // 512 chunks of 16B for A
            int chunk = tid + i * 128;
            int r = chunk >> 3, c = chunk & 7;
            const uint8_t* src = g_K8 + (size_t)(rowBase + r) * NN + kbase + c * 16;
            uint32_t dst = sA_u + buf * SA_BUF + r * 128 + ((c ^ (r & 7)) << 4);
            CP_ASYNC16(dst, src);
        }
#pragma unroll
        for (int i = 0; i < 3; i++) {            // 384 chunks for B (48 rows)
            int chunk = tid + i * 128;
            int r = chunk >> 3, c = chunk & 7;
            const uint8_t* src = g_pT8 + (size_t)r * NN + kbase + c * 16;
            uint32_t dst = sB_u + buf * SB_BUF + r * 128 + ((c ^ (r & 7)) << 4);
            CP_ASYNC16(dst, src);
        }
    };

    float d[6][4];
#pragma unroll
    for (int i = 0; i < 6; i++)
#pragma unroll
        for (int j = 0; j < 4; j++) d[i][j] = 0.0f;

    prefetch(0, 0); CP_COMMIT();
    prefetch(1, 1); CP_COMMIT();

    // swizzled chunk offsets for k-subtiles: chunk = kk*2 + hi, xor low3(row)=grp
    int ofs[4][2];
#pragma unroll
    for (int kk = 0; kk < 4; kk++) {
        ofs[kk][0] = (((kk * 2 + 0) ^ grp) << 4);
        ofs[kk][1] = (((kk * 2 + 1) ^ grp) << 4);
    }
    int aBase0 = (warp * 16 + grp) * 128 + tig * 4;
    int aBase1 = aBase0 + 8 * 128;

    for (int s = 0; s < NSTAGE; s++) {
        CP_WAIT1();
        __syncthreads();
        if (s + 2 < NSTAGE) prefetch(s + 2, (s + 2) % 3);
        CP_COMMIT();
        const uint8_t* A  = sA + (s % 3) * SA_BUF;
        const uint8_t* Bm = sB + (s % 3) * SB_BUF;
#pragma unroll
        for (int kk = 0; kk < 4; kk++) {
            uint32_t a0 = *reinterpret_cast<const uint32_t*>(A + aBase0 + ofs[kk][0]);
            uint32_t a1 = *reinterpret_cast<const uint32_t*>(A + aBase1 + ofs[kk][0]);
            uint32_t a2 = *reinterpret_cast<const uint32_t*>(A + aBase0 + ofs[kk][1]);
            uint32_t a3 = *reinterpret_cast<const uint32_t*>(A + aBase1 + ofs[kk][1]);
#pragma unroll
            for (int nt = 0; nt < 6; nt++) {
                int bb = (grp + nt * 8) * 128 + tig * 4;
                uint32_t b0 = *reinterpret_cast<const uint32_t*>(Bm + bb + ofs[kk][0]);
                uint32_t b1 = *reinterpret_cast<const uint32_t*>(Bm + bb + ofs[kk][1]);
                mma_fp8(d[nt], a0, a1, a2, a3, b0, b1);
            }
        }
    }

    float* outp = g_Bp[blockIdx.y];
    int row0 = rowBase + warp * 16 + grp;
#pragma unroll
    for (int nt = 0; nt < 3; nt++) {   // combine hi + lo/64
        int col = nt * 8 + 2 * tig;
        float v00 = d[nt][0] + d[nt + 3][0] * (1.0f / 64.0f);
        float v01 = d[nt][1] + d[nt + 3][1] * (1.0f / 64.0f);
        float v10 = d[nt][2] + d[nt + 3][2] * (1.0f / 64.0f);
        float v11 = d[nt][3] + d[nt + 3][3] * (1.0f / 64.0f);
        *reinterpret_cast<float2*>(&outp[(size_t)row0 * CP + col]) = make_float2(v00, v01);
        *reinterpret_cast<float2*>(&outp[(size_t)(row0 + 8) * CP + col]) = make_float2(v10, v11);
    }
}

// ---------------- fused update + softmax: q = u - S@Ws^T - B@Wb^T, then probs ----------------
__global__ void update_kernel(const float* __restrict__ u, float* __restrict__ outp, int last) {
    __shared__ float su[256 * CC];             // staged u tile (coalesced load)
    __shared__ float sws[CC * CC], swb[CC * CC];
    int tid = threadIdx.x;
    for (int t = tid; t < CC * CC; t += 256) { sws[t] = g_Ws[t]; swb[t] = g_Wb[t]; }
    int base = blockIdx.x * 256 * CC;
    for (int t = tid; t < 256 * CC; t += 256) su[t] = u[base + t];
    __syncthreads();
    int n = blockIdx.x * 256 + tid;

    float sv[CC], bv[CP];
#pragma unroll
    for (int c = 0; c < CC; c++) sv[c] = g_S[c * NN + n];
#pragma unroll
    for (int q4 = 0; q4 < 6; q4++) {
        float4 a = *reinterpret_cast<const float4*>(&g_Bp[0][(size_t)n * CP + q4 * 4]);
        float4 b = *reinterpret_cast<const float4*>(&g_Bp[1][(size_t)n * CP + q4 * 4]);
        float4 cc4 = *reinterpret_cast<const float4*>(&g_Bp[2][(size_t)n * CP + q4 * 4]);
        float4 e = *reinterpret_cast<const float4*>(&g_Bp[3][(size_t)n * CP + q4 * 4]);
        bv[q4 * 4 + 0] = a.x + b.x + cc4.x + e.x;
        bv[q4 * 4 + 1] = a.y + b.y + cc4.y + e.y;
        bv[q4 * 4 + 2] = a.z + b.z + cc4.z + e.z;
        bv[q4 * 4 + 3] = a.w + b.w + cc4.w + e.w;
    }

    float qn[CC];
#pragma unroll
    for (int k = 0; k < CC; k++) {
        float acc = 0.0f;
#pragma unroll
        for (int c = 0; c < CC; c++)
            acc += sws[k * CC + c] * sv[c] + swb[k * CC + c] * bv[c];
        qn[k] = su[tid * CC + k] - acc;
    }

    if (last) {
#pragma unroll
        for (int k = 0; k < CC; k++) outp[n * CC + k] = qn[k];
    } else {
        emit_probs(qn, n);
    }
}

// ---------------- launch ----------------
extern "C" void kernel_launch(void* const* d_in, const int* in_sizes, int n_in,
                              void* d_out, int out_size) {
    const float* u   = (const float*)d_in[0];
    const float* ref = (const float*)d_in[1];
    const float* ws  = (const float*)d_in[2];
    const float* wb  = (const float*)d_in[3];
    const float* cm  = (const float*)d_in[4];
    float* out = (float*)d_out;

    prep_kernel<<<36, 256>>>(ref, ws, wb, cm);
    build_k_kernel<<<dim3(18, 576), 128>>>();
    softmax0_kernel<<<36, 256>>>(u);

    for (int it = 0; it < 5; it++) {
        gemm_kernel<<<dim3(144, KSPLIT), 128>>>();
        conv_x_kernel<<<96, 288>>>();
        conv_y_kernel<<<dim3(12, 21), 96>>>();
        update_kernel<<<36, 256>>>(u, out, it == 4 ? 1 : 0);
    }
}

// round 5
// speedup vs baseline: 5.3729x; 1.0299x over previous
#include <cuda_runtime.h>
#include <cuda_fp16.h>
#include <cuda_fp8.h>
#include <cstdint>

#define HH 96
#define WW 96
#define CC 21
#define NN 9216          // HH*WW
#define CP 24            // padded channel count
#define BROWS 48         // B operand rows: 24 hi + 24 lo (residual)

#define KT 128           // k-tile (fp8 elements = bytes)
#define RB 64            // rows per gemm block
#define KSPLIT 4
#define KQ (NN / KSPLIT)      // 2304
#define NSTAGE (KQ / KT)      // 18
#define SA_BUF (RB * 128)     // 8192 B per stage
#define SB_BUF (BROWS * 128)  // 6144 B per stage

// ---------------- scratch (device globals; no allocation allowed) ----------------
__device__ uint8_t g_K8[(size_t)NN * NN];   // bilateral kernel, e4m3, ~85MB
__device__ __half  g_pT[CC * NN];           // probs planar [c][n], fp16 (conv path)
__device__ uint8_t g_pT8[BROWS * NN];       // probs e4m3 planar: rows 0-23 hi, 24-47 lo*64
__device__ float   g_tmp[CC * NN];          // conv intermediate, planar
__device__ float   g_S[CC * NN];            // spatial message, planar
__device__ float   g_Bp[KSPLIT][NN * CP];   // bilateral partials per k-split
__device__ float   g_G[HH * HH];            // 1D spatial gaussian G[a][b]
__device__ float   g_Ws[CC * CC];           // compat[k][c] * ws[c]
__device__ float   g_Wb[CC * CC];           // compat[k][c] * wb[c]
__device__ float   g_col[NN * 3];           // colors * 8 (= /theta_beta)

// ---------------- async / ldmatrix helpers ----------------
#define CP_ASYNC16(dst, src) \
    asm volatile("cp.async.cg.shared.global [%0], [%1], 16;\n" :: "r"(dst), "l"(src))
#define CP_COMMIT() asm volatile("cp.async.commit_group;\n" ::: "memory")
#define CP_WAIT1()  asm volatile("cp.async.wait_group 1;\n" ::: "memory")
#define LDSM4(r0, r1, r2, r3, addr) \
    asm volatile("ldmatrix.sync.aligned.m8n8.x4.shared.b16 {%0,%1,%2,%3}, [%4];" \
                 : "=r"(r0), "=r"(r1), "=r"(r2), "=r"(r3) : "r"(addr))

__device__ __forceinline__ uint8_t to_e4m3(float f) {
    return (uint8_t)__nv_cvt_float_to_fp8(f, __NV_SATFINITE, __NV_E4M3);
}
__device__ __forceinline__ float from_e4m3(uint8_t s) {
    return __half2float(__nv_cvt_fp8_to_halfraw((__nv_fp8_storage_t)s, __NV_E4M3));
}

// ---------------- prep ----------------
__global__ void prep_kernel(const float* __restrict__ ref, const float* __restrict__ ws,
                            const float* __restrict__ wb, const float* __restrict__ cm) {
    int t = blockIdx.x * 256 + threadIdx.x;
    if (t < NN) {
        g_col[t * 3 + 0] = ref[t * 3 + 0] * 8.0f;
        g_col[t * 3 + 1] = ref[t * 3 + 1] * 8.0f;
        g_col[t * 3 + 2] = ref[t * 3 + 2] * 8.0f;
    }
    if (t < HH * HH) {
        int a = t / HH, b = t % HH;
        float d = (float)(a - b);
        g_G[t] = __expf(-0.5f * d * d / 9.0f);   // theta_gamma = 3
    }
    if (t < CC * CC) {
        g_Ws[t] = cm[t] * ws[t % CC];
        g_Wb[t] = cm[t] * wb[t % CC];
    }
}

// ---------------- build bilateral kernel matrix (fp8, once) ----------------
__global__ void build_k_kernel() {
    int jq = blockIdx.x * 128 + threadIdx.x;   // quad of columns
    int j0 = jq * 4;
    int i0 = blockIdx.y * 16;
    float yj = (float)(j0 / WW), xj = (float)(j0 % WW);  // quad within one row
    float cr[4], cg[4], cb[4];
#pragma unroll
    for (int t = 0; t < 4; t++) {
        cr[t] = g_col[(j0 + t) * 3 + 0];
        cg[t] = g_col[(j0 + t) * 3 + 1];
        cb[t] = g_col[(j0 + t) * 3 + 2];
    }
#pragma unroll 4
    for (int t = 0; t < 16; t++) {
        int i = i0 + t;
        float yi = (float)(i / WW), xi = (float)(i % WW);
        float ri = g_col[i * 3 + 0], gi = g_col[i * 3 + 1], bi = g_col[i * 3 + 2];
        float dy = yi - yj;
        uint32_t packed = 0;
#pragma unroll
        for (int s = 0; s < 4; s++) {
            float dx = xi - (xj + (float)s);
            float d2 = (dy * dy + dx * dx) * (1.0f / 64.0f);
            float dr = ri - cr[s], dg = gi - cg[s], db = bi - cb[s];
            d2 += dr * dr + dg * dg + db * db;
            packed |= (uint32_t)to_e4m3(__expf(-0.5f * d2)) << (8 * s);
        }
        *reinterpret_cast<uint32_t*>(&g_K8[(size_t)i * NN + j0]) = packed;
    }
}

// ---------------- prob emission (shared by softmax0 and update) ----------------
__device__ __forceinline__ void emit_probs(const float* v, int n) {
    float mx = -1e30f;
#pragma unroll
    for (int c = 0; c < CC; c++) mx = fmaxf(mx, v[c]);
    float s = 0.0f;
    float e[CC];
#pragma unroll
    for (int c = 0; c < CC; c++) { e[c] = __expf(v[c] - mx); s += e[c]; }
    float inv = 1.0f / s;
#pragma unroll
    for (int c = 0; c < CC; c++) {
        float p = e[c] * inv;
        g_pT[c * NN + n] = __float2half_rn(p);
        uint8_t hi = to_e4m3(p);
        float res = 64.0f * (p - from_e4m3(hi));
        g_pT8[c * NN + n] = hi;
        g_pT8[(CP + c) * NN + n] = to_e4m3(res);
    }
#pragma unroll
    for (int c = CC; c < CP; c++) {
        g_pT8[c * NN + n] = 0;
        g_pT8[(CP + c) * NN + n] = 0;
    }
}

__global__ void softmax0_kernel(const float* __restrict__ u) {
    int n = blockIdx.x * 256 + threadIdx.x;
    float v[CC];
#pragma unroll
    for (int c = 0; c < CC; c++) v[c] = u[n * CC + c];
    emit_probs(v, n);
}

// ---------------- separable spatial filtering (exact) ----------------
__global__ void conv_x_kernel() {   // grid = 96 (y), block = 288 (x + 96*cg), cg: 7 ch each
    __shared__ float sp[CC * WW];
    int y = blockIdx.x;
    int tid = threadIdx.x;
    for (int t = tid; t < CC * WW; t += 288)
        sp[t] = __half2float(g_pT[(t / WW) * NN + y * WW + (t % WW)]);
    __syncthreads();
    int x = tid % 96, cg = tid / 96;
    int c0 = cg * 7;
    float acc[7];
#pragma unroll
    for (int i = 0; i < 7; i++) acc[i] = 0.0f;
#pragma unroll 4
    for (int xp = 0; xp < WW; xp++) {
        float g = g_G[xp * WW + x];
#pragma unroll
        for (int i = 0; i < 7; i++) acc[i] += g * sp[(c0 + i) * WW + xp];
    }
#pragma unroll
    for (int i = 0; i < 7; i++)
        g_tmp[(c0 + i) * NN + y * WW + x] = acc[i];
}

__global__ void conv_y_kernel() {   // grid = (12 ytile, 21 c), block = 96 (x)
    __shared__ float gsh[8][HH];
    int c = blockIdx.y, y0 = blockIdx.x * 8, x = threadIdx.x;
    for (int t = threadIdx.x; t < 8 * HH; t += 96)
        gsh[t / HH][t % HH] = g_G[(y0 + t / HH) * HH + (t % HH)];
    __syncthreads();
    float acc[8];
#pragma unroll
    for (int i = 0; i < 8; i++) acc[i] = 0.0f;
    const float* tp = g_tmp + c * NN + x;
#pragma unroll 4
    for (int yp = 0; yp < HH; yp++) {
        float v = tp[yp * WW];
#pragma unroll
        for (int i = 0; i < 8; i++) acc[i] += gsh[i][yp] * v;
    }
#pragma unroll
    for (int i = 0; i < 8; i++)
        g_S[c * NN + (y0 + i) * WW + x] = acc[i];
}

// ---------------- fp8 GEMM: Bp = K8 @ pT8^T (hi & lo), cp.async + ldmatrix ----------------
__device__ __forceinline__ void mma_fp8(float* d, uint32_t a0, uint32_t a1, uint32_t a2,
                                        uint32_t a3, uint32_t b0, uint32_t b1) {
    asm volatile(
        "mma.sync.aligned.m16n8k32.row.col.f32.e4m3.e4m3.f32 "
        "{%0,%1,%2,%3},{%4,%5,%6,%7},{%8,%9},{%0,%1,%2,%3};\n"
        : "+f"(d[0]), "+f"(d[1]), "+f"(d[2]), "+f"(d[3])
        : "r"(a0), "r"(a1), "r"(a2), "r"(a3), "r"(b0), "r"(b1));
}

__global__ void __launch_bounds__(128, 4) gemm_kernel() {
    // grid = (144, KSPLIT), block = 128 (4 warps). Block: 64 rows, quarter K range.
    __shared__ __align__(16) uint8_t sA[3 * SA_BUF];   // 24576 B
    __shared__ __align__(16) uint8_t sB[3 * SB_BUF];   // 18432 B
    int tid = threadIdx.x;
    int warp = tid >> 5, lane = tid & 31;
    int grp = lane >> 2, tig = lane & 3;
    int rowBase = blockIdx.x * RB;
    size_t kb0 = (size_t)blockIdx.y * KQ;

    uint32_t sA_u = (uint32_t)__cvta_generic_to_shared(&sA[0]);
    uint32_t sB_u = (uint32_t)__cvta_generic_to_shared(&sB[0]);

    auto prefetch = [&](int s, int buf) {
        size_t kbase = kb0 + (size_t)s * KT;
#pragma unroll
        for (int i = 0; i < 4; i++) {            // 512 chunks of 16B for A
            int chunk = tid + i * 128;
            int r = chunk >> 3, c = chunk & 7;
            const uint8_t* src = g_K8 + (size_t)(rowBase + r) * NN + kbase + c * 16;
            uint32_t dst = sA_u + buf * SA_BUF + r * 128 + ((c ^ (r & 7)) << 4);
            CP_ASYNC16(dst, src);
        }
#pragma unroll
        for (int i = 0; i < 3; i++) {            // 384 chunks for B (48 rows)
            int chunk = tid + i * 128;
            int r = chunk >> 3, c = chunk & 7;
            const uint8_t* src = g_pT8 + (size_t)r * NN + kbase + c * 16;
            uint32_t dst = sB_u + buf * SB_BUF + r * 128 + ((c ^ (r & 7)) << 4);
            CP_ASYNC16(dst, src);
        }
    };

    float d[6][4];
#pragma unroll
    for (int i = 0; i < 6; i++)
#pragma unroll
        for (int j = 0; j < 4; j++) d[i][j] = 0.0f;

    prefetch(0, 0); CP_COMMIT();
    prefetch(1, 1); CP_COMMIT();

    // ---- ldmatrix address setup (all loop-invariant per thread) ----
    int l7 = lane & 7;
    int aHalf = lane >> 4;              // A: which 16B half of the k32 chunk
    int bHalf = (lane >> 3) & 1;        // B: which 16B half
    int aRow = warp * 16 + ((lane >> 3) & 1) * 8 + l7;
    uint32_t aBase = sA_u + (uint32_t)aRow * 128;
    uint32_t bBase[3];
#pragma unroll
    for (int p = 0; p < 3; p++)
        bBase[p] = sB_u + (uint32_t)(((2 * p + (lane >> 4)) * 8 + l7) * 128);
    int offA[4], offB[4];
#pragma unroll
    for (int kk = 0; kk < 4; kk++) {
        offA[kk] = (((2 * kk + aHalf) ^ l7) << 4);
        offB[kk] = (((2 * kk + bHalf) ^ l7) << 4);
    }

    for (int s = 0; s < NSTAGE; s++) {
        CP_WAIT1();
        __syncthreads();
        if (s + 2 < NSTAGE) prefetch(s + 2, (s + 2) % 3);
        CP_COMMIT();
        uint32_t As = aBase + (s % 3) * SA_BUF;
        uint32_t B0 = bBase[0] + (s % 3) * SB_BUF;
        uint32_t B1 = bBase[1] + (s % 3) * SB_BUF;
        uint32_t B2 = bBase[2] + (s % 3) * SB_BUF;
#pragma unroll
        for (int kk = 0; kk < 4; kk++) {
            uint32_t a0, a1, a2, a3;
            LDSM4(a0, a1, a2, a3, As + offA[kk]);
            uint32_t b00, b01, b10, b11;
            LDSM4(b00, b01, b10, b11, B0 + offB[kk]);   // nt0 (b00,b01), nt1 (b10,b11)
            uint32_t b20, b21, b30, b31;
            LDSM4(b20, b21, b30, b31, B1 + offB[kk]);   // nt2, nt3
            uint32_t b40, b41, b50, b51;
            LDSM4(b40, b41, b50, b51, B2 + offB[kk]);   // nt4, nt5
            mma_fp8(d[0], a0, a1, a2, a3, b00, b01);
            mma_fp8(d[1], a0, a1, a2, a3, b10, b11);
            mma_fp8(d[2], a0, a1, a2, a3, b20, b21);
            mma_fp8(d[3], a0, a1, a2, a3, b30, b31);
            mma_fp8(d[4], a0, a1, a2, a3, b40, b41);
            mma_fp8(d[5], a0, a1, a2, a3, b50, b51);
        }
    }

    // nt order in memory rows: 0,1 = hi cols 0-15; 2 = hi 16-23; 3 = lo 0-7; 4,5 = lo 8-23
    // hi row n: rows 0-23 -> nt = n/8 in {0,1,2}; lo row: 24+n -> nt 3,4,5
    float* outp = g_Bp[blockIdx.y];
    int row0 = rowBase + warp * 16 + grp;
#pragma unroll
    for (int nt = 0; nt < 3; nt++) {   // combine hi + lo/64
        int col = nt * 8 + 2 * tig;
        float v00 = d[nt][0] + d[nt + 3][0] * (1.0f / 64.0f);
        float v01 = d[nt][1] + d[nt + 3][1] * (1.0f / 64.0f);
        float v10 = d[nt][2] + d[nt + 3][2] * (1.0f / 64.0f);
        float v11 = d[nt][3] + d[nt + 3][3] * (1.0f / 64.0f);
        *reinterpret_cast<float2*>(&outp[(size_t)row0 * CP + col]) = make_float2(v00, v01);
        *reinterpret_cast<float2*>(&outp[(size_t)(row0 + 8) * CP + col]) = make_float2(v10, v11);
    }
}

// ---------------- fused update + softmax: q = u - S@Ws^T - B@Wb^T, then probs ----------------
__global__ void update_kernel(const float* __restrict__ u, float* __restrict__ outp, int last) {
    __shared__ float su[256 * CC];
    __shared__ float sws[CC * CC], swb[CC * CC];
    int tid = threadIdx.x;
    for (int t = tid; t < CC * CC; t += 256) { sws[t] = g_Ws[t]; swb[t] = g_Wb[t]; }
    int base = blockIdx.x * 256 * CC;
    for (int t = tid; t < 256 * CC; t += 256) su[t] = u[base + t];
    __syncthreads();
    int n = blockIdx.x * 256 + tid;

    float sv[CC], bv[CP];
#pragma unroll
    for (int c = 0; c < CC; c++) sv[c] = g_S[c * NN + n];
#pragma unroll
    for (int q4 = 0; q4 < 6; q4++) {
        float4 a = *reinterpret_cast<const float4*>(&g_Bp[0][(size_t)n * CP + q4 * 4]);
        float4 b = *reinterpret_cast<const float4*>(&g_Bp[1][(size_t)n * CP + q4 * 4]);
        float4 cc4 = *reinterpret_cast<const float4*>(&g_Bp[2][(size_t)n * CP + q4 * 4]);
        float4 e = *reinterpret_cast<const float4*>(&g_Bp[3][(size_t)n * CP + q4 * 4]);
        bv[q4 * 4 + 0] = a.x + b.x + cc4.x + e.x;
        bv[q4 * 4 + 1] = a.y + b.y + cc4.y + e.y;
        bv[q4 * 4 + 2] = a.z + b.z + cc4.z + e.z;
        bv[q4 * 4 + 3] = a.w + b.w + cc4.w + e.w;
    }

    float qn[CC];
#pragma unroll
    for (int k = 0; k < CC; k++) {
        float acc = 0.0f;
#pragma unroll
        for (int c = 0; c < CC; c++)
            acc += sws[k * CC + c] * sv[c] + swb[k * CC + c] * bv[c];
        qn[k] = su[tid * CC + k] - acc;
    }

    if (last) {
#pragma unroll
        for (int k = 0; k < CC; k++) outp[n * CC + k] = qn[k];
    } else {
        emit_probs(qn, n);
    }
}

// ---------------- launch ----------------
extern "C" void kernel_launch(void* const* d_in, const int* in_sizes, int n_in,
                              void* d_out, int out_size) {
    const float* u   = (const float*)d_in[0];
    const float* ref = (const float*)d_in[1];
    const float* ws  = (const float*)d_in[2];
    const float* wb  = (const float*)d_in[3];
    const float* cm  = (const float*)d_in[4];
    float* out = (float*)d_out;

    prep_kernel<<<36, 256>>>(ref, ws, wb, cm);
    build_k_kernel<<<dim3(18, 576), 128>>>();
    softmax0_kernel<<<36, 256>>>(u);

    for (int it = 0; it < 5; it++) {
        gemm_kernel<<<dim3(144, KSPLIT), 128>>>();
        conv_x_kernel<<<96, 288>>>();
        conv_y_kernel<<<dim3(12, 21), 96>>>();
        update_kernel<<<36, 256>>>(u, out, it == 4 ? 1 : 0);
    }
}

// round 6
// speedup vs baseline: 6.6092x; 1.2301x over previous
#include <cuda_runtime.h>
#include <cuda_fp16.h>
#include <cuda_fp8.h>
#include <cstdint>

#define HH 96
#define WW 96
#define CC 21
#define NN 9216          // HH*WW
#define CP 24            // padded channel count
#define BROWS 48         // B operand rows: 24 hi + 24 lo (residual)

#define KT 128           // k-tile (fp8 elements = bytes)
#define RB 128           // rows per gemm block (4 warps x m32)
#define KSPLIT 4
#define KQ (NN / KSPLIT)      // 2304
#define NSTAGE (KQ / KT)      // 18
#define SA_BUF (RB * 128)     // 16384 B per stage
#define SB_BUF (BROWS * 128)  // 6144 B per stage

// ---------------- scratch (device globals; no allocation allowed) ----------------
__device__ uint8_t g_K8[(size_t)NN * NN];   // bilateral kernel, e4m3, ~85MB
__device__ __half  g_pT[CC * NN];           // probs planar [c][n], fp16 (conv path)
__device__ uint8_t g_pT8[BROWS * NN];       // probs e4m3 planar: rows 0-23 hi, 24-47 lo*64
__device__ float   g_tmp[CC * NN];          // conv intermediate, planar
__device__ float   g_S[CC * NN];            // spatial message, planar
__device__ float   g_Bp[KSPLIT][NN * CP];   // bilateral partials per k-split
__device__ float   g_G[HH * HH];            // 1D spatial gaussian G[a][b]
__device__ float   g_Ws[CC * CC];           // compat[k][c] * ws[c]
__device__ float   g_Wb[CC * CC];           // compat[k][c] * wb[c]
__device__ float   g_col[NN * 3];           // colors * 8 (= /theta_beta)

// ---------------- async / ldmatrix helpers ----------------
#define CP_ASYNC16(dst, src) \
    asm volatile("cp.async.cg.shared.global [%0], [%1], 16;\n" :: "r"(dst), "l"(src))
#define CP_COMMIT() asm volatile("cp.async.commit_group;\n" ::: "memory")
#define CP_WAIT1()  asm volatile("cp.async.wait_group 1;\n" ::: "memory")
#define LDSM4(r0, r1, r2, r3, addr) \
    asm volatile("ldmatrix.sync.aligned.m8n8.x4.shared.b16 {%0,%1,%2,%3}, [%4];" \
                 : "=r"(r0), "=r"(r1), "=r"(r2), "=r"(r3) : "r"(addr))

__device__ __forceinline__ uint8_t to_e4m3(float f) {
    return (uint8_t)__nv_cvt_float_to_fp8(f, __NV_SATFINITE, __NV_E4M3);
}
__device__ __forceinline__ float from_e4m3(uint8_t s) {
    return __half2float(__nv_cvt_fp8_to_halfraw((__nv_fp8_storage_t)s, __NV_E4M3));
}

// ---------------- prep ----------------
__global__ void prep_kernel(const float* __restrict__ ref, const float* __restrict__ ws,
                            const float* __restrict__ wb, const float* __restrict__ cm) {
    int t = blockIdx.x * 256 + threadIdx.x;
    if (t < NN) {
        g_col[t * 3 + 0] = ref[t * 3 + 0] * 8.0f;
        g_col[t * 3 + 1] = ref[t * 3 + 1] * 8.0f;
        g_col[t * 3 + 2] = ref[t * 3 + 2] * 8.0f;
    }
    if (t < HH * HH) {
        int a = t / HH, b = t % HH;
        float d = (float)(a - b);
        g_G[t] = __expf(-0.5f * d * d / 9.0f);   // theta_gamma = 3
    }
    if (t < CC * CC) {
        g_Ws[t] = cm[t] * ws[t % CC];
        g_Wb[t] = cm[t] * wb[t % CC];
    }
}

// ---------------- build bilateral kernel matrix (fp8, once) ----------------
// exp(-0.5*d2) < e4m3 round-to-zero threshold (2^-10 midpoint) when d2 > 13.86,
// so skipping the expf there is numerically identical to computing it.
__global__ void build_k_kernel() {
    int jq = blockIdx.x * 128 + threadIdx.x;   // quad of columns
    int j0 = jq * 4;
    int i0 = blockIdx.y * 16;
    float yj = (float)(j0 / WW), xj = (float)(j0 % WW);  // quad within one row
    float cr[4], cg[4], cb[4];
#pragma unroll
    for (int t = 0; t < 4; t++) {
        cr[t] = g_col[(j0 + t) * 3 + 0];
        cg[t] = g_col[(j0 + t) * 3 + 1];
        cb[t] = g_col[(j0 + t) * 3 + 2];
    }
#pragma unroll 2
    for (int t = 0; t < 16; t++) {
        int i = i0 + t;
        float yi = (float)(i / WW), xi = (float)(i % WW);
        float ri = g_col[i * 3 + 0], gi = g_col[i * 3 + 1], bi = g_col[i * 3 + 2];
        float dy = yi - yj;
        float d2v[4];
        bool nearv = false;
#pragma unroll
        for (int s = 0; s < 4; s++) {
            float dx = xi - (xj + (float)s);
            float d2 = (dy * dy + dx * dx) * (1.0f / 64.0f);
            float dr = ri - cr[s], dg = gi - cg[s], db = bi - cb[s];
            d2 += dr * dr + dg * dg + db * db;
            d2v[s] = d2;
            nearv |= (d2 < 13.86f);
        }
        uint32_t packed = 0;
        if (__ballot_sync(0xffffffffu, nearv)) {   // whole warp far -> skip all MUFU
            if (nearv) {
#pragma unroll
                for (int s = 0; s < 4; s++) {
                    float e = (d2v[s] < 13.86f) ? __expf(-0.5f * d2v[s]) : 0.0f;
                    packed |= (uint32_t)to_e4m3(e) << (8 * s);
                }
            }
        }
        *reinterpret_cast<uint32_t*>(&g_K8[(size_t)i * NN + j0]) = packed;
    }
}

// ---------------- prob emission (shared by softmax0 and update) ----------------
__device__ __forceinline__ void emit_probs(const float* v, int n) {
    float mx = -1e30f;
#pragma unroll
    for (int c = 0; c < CC; c++) mx = fmaxf(mx, v[c]);
    float s = 0.0f;
    float e[CC];
#pragma unroll
    for (int c = 0; c < CC; c++) { e[c] = __expf(v[c] - mx); s += e[c]; }
    float inv = 1.0f / s;
#pragma unroll
    for (int c = 0; c < CC; c++) {
        float p = e[c] * inv;
        g_pT[c * NN + n] = __float2half_rn(p);
        uint8_t hi = to_e4m3(p);
        float res = 64.0f * (p - from_e4m3(hi));
        g_pT8[c * NN + n] = hi;
        g_pT8[(CP + c) * NN + n] = to_e4m3(res);
    }
#pragma unroll
    for (int c = CC; c < CP; c++) {
        g_pT8[c * NN + n] = 0;
        g_pT8[(CP + c) * NN + n] = 0;
    }
}

__global__ void softmax0_kernel(const float* __restrict__ u) {
    int n = blockIdx.x * 256 + threadIdx.x;
    float v[CC];
#pragma unroll
    for (int c = 0; c < CC; c++) v[c] = u[n * CC + c];
    emit_probs(v, n);
}

// ---------------- separable spatial filtering (exact) ----------------
__global__ void conv_x_kernel() {   // grid = 96 (y), block = 288 (x + 96*cg), cg: 7 ch each
    __shared__ float sp[CC * WW];
    int y = blockIdx.x;
    int tid = threadIdx.x;
    for (int t = tid; t < CC * WW; t += 288)
        sp[t] = __half2float(g_pT[(t / WW) * NN + y * WW + (t % WW)]);
    __syncthreads();
    int x = tid % 96, cg = tid / 96;
    int c0 = cg * 7;
    float acc[7];
#pragma unroll
    for (int i = 0; i < 7; i++) acc[i] = 0.0f;
#pragma unroll 4
    for (int xp = 0; xp < WW; xp++) {
        float g = g_G[xp * WW + x];
#pragma unroll
        for (int i = 0; i < 7; i++) acc[i] += g * sp[(c0 + i) * WW + xp];
    }
#pragma unroll
    for (int i = 0; i < 7; i++)
        g_tmp[(c0 + i) * NN + y * WW + x] = acc[i];
}

__global__ void conv_y_kernel() {   // grid = (12 ytile, 21 c), block = 96 (x)
    __shared__ float gsh[8][HH];
    int c = blockIdx.y, y0 = blockIdx.x * 8, x = threadIdx.x;
    for (int t = threadIdx.x; t < 8 * HH; t += 96)
        gsh[t / HH][t % HH] = g_G[(y0 + t / HH) * HH + (t % HH)];
    __syncthreads();
    float acc[8];
#pragma unroll
    for (int i = 0; i < 8; i++) acc[i] = 0.0f;
    const float* tp = g_tmp + c * NN + x;
#pragma unroll 4
    for (int yp = 0; yp < HH; yp++) {
        float v = tp[yp * WW];
#pragma unroll
        for (int i = 0; i < 8; i++) acc[i] += gsh[i][yp] * v;
    }
#pragma unroll
    for (int i = 0; i < 8; i++)
        g_S[c * NN + (y0 + i) * WW + x] = acc[i];
}

// ---------------- fp8 GEMM: Bp = K8 @ pT8^T (hi & lo), m32 warp tiles ----------------
__device__ __forceinline__ void mma_fp8(float* d, uint32_t a0, uint32_t a1, uint32_t a2,
                                        uint32_t a3, uint32_t b0, uint32_t b1) {
    asm volatile(
        "mma.sync.aligned.m16n8k32.row.col.f32.e4m3.e4m3.f32 "
        "{%0,%1,%2,%3},{%4,%5,%6,%7},{%8,%9},{%0,%1,%2,%3};\n"
        : "+f"(d[0]), "+f"(d[1]), "+f"(d[2]), "+f"(d[3])
        : "r"(a0), "r"(a1), "r"(a2), "r"(a3), "r"(b0), "r"(b1));
}

__global__ void __launch_bounds__(128, 2) gemm_kernel() {
    // grid = (72, KSPLIT), block = 128 (4 warps). Block: 128 rows, quarter K range.
    // Each warp: 32 rows (two m16 tiles) x 24 cols (hi) + 24 cols (lo residual).
    __shared__ __align__(16) uint8_t sA[3 * SA_BUF];   // 49152 B
    __shared__ __align__(16) uint8_t sB[3 * SB_BUF];   // 18432 B
    int tid = threadIdx.x;
    int warp = tid >> 5, lane = tid & 31;
    int grp = lane >> 2, tig = lane & 3;
    int rowBase = blockIdx.x * RB;
    size_t kb0 = (size_t)blockIdx.y * KQ;

    uint32_t sA_u = (uint32_t)__cvta_generic_to_shared(&sA[0]);
    uint32_t sB_u = (uint32_t)__cvta_generic_to_shared(&sB[0]);

    auto prefetch = [&](int s, int buf) {
        size_t kbase = kb0 + (size_t)s * KT;
#pragma unroll
        for (int i = 0; i < 8; i++) {            // 1024 chunks of 16B for A (128 rows)
            int chunk = tid + i * 128;
            int r = chunk >> 3, c = chunk & 7;
            const uint8_t* src = g_K8 + (size_t)(rowBase + r) * NN + kbase + c * 16;
            uint32_t dst = sA_u + buf * SA_BUF + r * 128 + ((c ^ (r & 7)) << 4);
            CP_ASYNC16(dst, src);
        }
#pragma unroll
        for (int i = 0; i < 3; i++) {            // 384 chunks for B (48 rows)
            int chunk = tid + i * 128;
            int r = chunk >> 3, c = chunk & 7;
            const uint8_t* src = g_pT8 + (size_t)r * NN + kbase + c * 16;
            uint32_t dst = sB_u + buf * SB_BUF + r * 128 + ((c ^ (r & 7)) << 4);
            CP_ASYNC16(dst, src);
        }
    };

    float d[2][6][4];
#pragma unroll
    for (int m = 0; m < 2; m++)
#pragma unroll
        for (int i = 0; i < 6; i++)
#pragma unroll
            for (int j = 0; j < 4; j++) d[m][i][j] = 0.0f;

    prefetch(0, 0); CP_COMMIT();
    prefetch(1, 1); CP_COMMIT();

    // ---- ldmatrix address setup (loop-invariant) ----
    int l7 = lane & 7;
    int aHalf = lane >> 4;
    int bHalf = (lane >> 3) & 1;
    uint32_t aBase[2];
#pragma unroll
    for (int m = 0; m < 2; m++) {
        int aRow = warp * 32 + m * 16 + ((lane >> 3) & 1) * 8 + l7;
        aBase[m] = sA_u + (uint32_t)aRow * 128;
    }
    uint32_t bBase[3];
#pragma unroll
    for (int p = 0; p < 3; p++)
        bBase[p] = sB_u + (uint32_t)(((2 * p + (lane >> 4)) * 8 + l7) * 128);
    int offA[4], offB[4];
#pragma unroll
    for (int kk = 0; kk < 4; kk++) {
        offA[kk] = (((2 * kk + aHalf) ^ l7) << 4);
        offB[kk] = (((2 * kk + bHalf) ^ l7) << 4);
    }

    int buf = 0;
    for (int s = 0; s < NSTAGE; s++) {
        CP_WAIT1();
        __syncthreads();
        if (s + 2 < NSTAGE) prefetch(s + 2, (s + 2) % 3);
        CP_COMMIT();
        uint32_t A0 = aBase[0] + buf * SA_BUF;
        uint32_t A1 = aBase[1] + buf * SA_BUF;
        uint32_t B0 = bBase[0] + buf * SB_BUF;
        uint32_t B1 = bBase[1] + buf * SB_BUF;
        uint32_t B2 = bBase[2] + buf * SB_BUF;
        buf = (buf == 2) ? 0 : buf + 1;
#pragma unroll
        for (int kk = 0; kk < 4; kk++) {
            uint32_t a00, a01, a02, a03, a10, a11, a12, a13;
            LDSM4(a00, a01, a02, a03, A0 + offA[kk]);
            LDSM4(a10, a11, a12, a13, A1 + offA[kk]);
            uint32_t b00, b01, b10, b11;
            LDSM4(b00, b01, b10, b11, B0 + offB[kk]);
            uint32_t b20, b21, b30, b31;
            LDSM4(b20, b21, b30, b31, B1 + offB[kk]);
            uint32_t b40, b41, b50, b51;
            LDSM4(b40, b41, b50, b51, B2 + offB[kk]);
            mma_fp8(d[0][0], a00, a01, a02, a03, b00, b01);
            mma_fp8(d[0][1], a00, a01, a02, a03, b10, b11);
            mma_fp8(d[0][2], a00, a01, a02, a03, b20, b21);
            mma_fp8(d[0][3], a00, a01, a02, a03, b30, b31);
            mma_fp8(d[0][4], a00, a01, a02, a03, b40, b41);
            mma_fp8(d[0][5], a00, a01, a02, a03, b50, b51);
            mma_fp8(d[1][0], a10, a11, a12, a13, b00, b01);
            mma_fp8(d[1][1], a10, a11, a12, a13, b10, b11);
            mma_fp8(d[1][2], a10, a11, a12, a13, b20, b21);
            mma_fp8(d[1][3], a10, a11, a12, a13, b30, b31);
            mma_fp8(d[1][4], a10, a11, a12, a13, b40, b41);
            mma_fp8(d[1][5], a10, a11, a12, a13, b50, b51);
        }
    }

    float* outp = g_Bp[blockIdx.y];
#pragma unroll
    for (int m = 0; m < 2; m++) {
        int row0 = rowBase + warp * 32 + m * 16 + grp;
#pragma unroll
        for (int nt = 0; nt < 3; nt++) {   // combine hi + lo/64
            int col = nt * 8 + 2 * tig;
            float v00 = d[m][nt][0] + d[m][nt + 3][0] * (1.0f / 64.0f);
            float v01 = d[m][nt][1] + d[m][nt + 3][1] * (1.0f / 64.0f);
            float v10 = d[m][nt][2] + d[m][nt + 3][2] * (1.0f / 64.0f);
            float v11 = d[m][nt][3] + d[m][nt + 3][3] * (1.0f / 64.0f);
            *reinterpret_cast<float2*>(&outp[(size_t)row0 * CP + col]) = make_float2(v00, v01);
            *reinterpret_cast<float2*>(&outp[(size_t)(row0 + 8) * CP + col]) = make_float2(v10, v11);
        }
    }
}

// ---------------- fused update + softmax: q = u - S@Ws^T - B@Wb^T, then probs ----------------
__global__ void update_kernel(const float* __restrict__ u, float* __restrict__ outp, int last) {
    __shared__ float su[256 * CC];
    __shared__ float sws[CC * CC], swb[CC * CC];
    int tid = threadIdx.x;
    for (int t = tid; t < CC * CC; t += 256) { sws[t] = g_Ws[t]; swb[t] = g_Wb[t]; }
    int base = blockIdx.x * 256 * CC;
    for (int t = tid; t < 256 * CC; t += 256) su[t] = u[base + t];
    __syncthreads();
    int n = blockIdx.x * 256 + tid;

    float sv[CC], bv[CP];
#pragma unroll
    for (int c = 0; c < CC; c++) sv[c] = g_S[c * NN + n];
#pragma unroll
    for (int q4 = 0; q4 < 6; q4++) {
        float4 a = *reinterpret_cast<const float4*>(&g_Bp[0][(size_t)n * CP + q4 * 4]);
        float4 b = *reinterpret_cast<const float4*>(&g_Bp[1][(size_t)n * CP + q4 * 4]);
        float4 cc4 = *reinterpret_cast<const float4*>(&g_Bp[2][(size_t)n * CP + q4 * 4]);
        float4 e = *reinterpret_cast<const float4*>(&g_Bp[3][(size_t)n * CP + q4 * 4]);
        bv[q4 * 4 + 0] = a.x + b.x + cc4.x + e.x;
        bv[q4 * 4 + 1] = a.y + b.y + cc4.y + e.y;
        bv[q4 * 4 + 2] = a.z + b.z + cc4.z + e.z;
        bv[q4 * 4 + 3] = a.w + b.w + cc4.w + e.w;
    }

    float qn[CC];
#pragma unroll
    for (int k = 0; k < CC; k++) {
        float acc = 0.0f;
#pragma unroll
        for (int c = 0; c < CC; c++)
            acc += sws[k * CC + c] * sv[c] + swb[k * CC + c] * bv[c];
        qn[k] = su[tid * CC + k] - acc;
    }

    if (last) {
#pragma unroll
        for (int k = 0; k < CC; k++) outp[n * CC + k] = qn[k];
    } else {
        emit_probs(qn, n);
    }
}

// ---------------- launch: fork-join DAG (convs overlap gemm; softmax0+convs overlap build_k) --
extern "C" void kernel_launch(void* const* d_in, const int* in_sizes, int n_in,
                              void* d_out, int out_size) {
    const float* u   = (const float*)d_in[0];
    const float* ref = (const float*)d_in[1];
    const float* ws  = (const float*)d_in[2];
    const float* wb  = (const float*)d_in[3];
    const float* cm  = (const float*)d_in[4];
    float* out = (float*)d_out;

    static cudaStream_t s2 = nullptr;
    static cudaEvent_t eFork = nullptr, eEmit = nullptr, eConv = nullptr;
    if (s2 == nullptr) {
        cudaStreamCreateWithFlags(&s2, cudaStreamNonBlocking);
        cudaEventCreateWithFlags(&eFork, cudaEventDisableTiming);
        cudaEventCreateWithFlags(&eEmit, cudaEventDisableTiming);
        cudaEventCreateWithFlags(&eConv, cudaEventDisableTiming);
    }

    // fork side stream off the main (legacy) stream
    cudaEventRecord(eFork, 0);
    cudaStreamWaitEvent(s2, eFork, 0);

    // main: prep -> build_K (long). side: softmax0 -> convs (independent of K).
    prep_kernel<<<36, 256>>>(ref, ws, wb, cm);
    build_k_kernel<<<dim3(18, 576), 128>>>();

    softmax0_kernel<<<36, 256, 0, s2>>>(u);
    cudaEventRecord(eEmit, s2);      // probs ready (iteration 0)

    for (int it = 0; it < 5; it++) {
        if (it > 0) cudaStreamWaitEvent(s2, eEmit, 0);
        conv_x_kernel<<<96, 288, 0, s2>>>();
        conv_y_kernel<<<dim3(12, 21), 96, 0, s2>>>();
        cudaEventRecord(eConv, s2);

        if (it == 0) cudaStreamWaitEvent(0, eEmit, 0);  // gemm needs softmax0
        gemm_kernel<<<dim3(72, KSPLIT), 128>>>();

        cudaStreamWaitEvent(0, eConv, 0);                // update needs convs
        update_kernel<<<36, 256>>>(u, out, it == 4 ? 1 : 0);
        if (it < 4) cudaEventRecord(eEmit, 0);           // new probs for next iter
    }
}

// round 7
// speedup vs baseline: 7.5223x; 1.1382x over previous
#include <cuda_runtime.h>
#include <cuda_fp16.h>
#include <cuda_fp8.h>
#include <cstdint>

#define HH 96
#define WW 96
#define CC 21
#define NN 9216          // HH*WW
#define CP 24            // padded channel count
#define BROWS 48         // B operand rows: 24 hi + 24 lo (residual)

#define KT 128           // k-tile (fp8 elements = bytes)
#define RB 128           // rows per gemm block (4 warps x m32)
#define KSPLIT 4
#define SA_BUF (RB * 128)     // 16384 B per stage
#define SB_BUF (BROWS * 128)  // 6144 B per stage

// ---------------- scratch (device globals; no allocation allowed) ----------------
__device__ uint8_t g_K8[(size_t)NN * NN];   // bilateral kernel, e4m3, ~85MB
__device__ __half  g_pT[CC * NN];           // probs planar [c][n], fp16 (conv path)
__device__ uint8_t g_pT8[BROWS * NN];       // probs e4m3 planar: rows 0-23 hi, 24-47 lo*64
__device__ float   g_tmp[CC * NN];          // conv intermediate, planar
__device__ float   g_S[CC * NN];            // spatial message, planar
__device__ float   g_Bp[KSPLIT][NN * CP];   // bilateral partials per k-split
__device__ float   g_G[HH * HH];            // 1D spatial gaussian G[a][b]
__device__ float   g_Ws[CC * CC];           // compat[k][c] * ws[c]
__device__ float   g_Wb[CC * CC];           // compat[k][c] * wb[c]
__device__ float   g_col[NN * 3];           // colors * 8 (= /theta_beta)

// ---------------- async / ldmatrix helpers ----------------
#define CP_ASYNC16(dst, src) \
    asm volatile("cp.async.cg.shared.global [%0], [%1], 16;\n" :: "r"(dst), "l"(src))
#define CP_COMMIT() asm volatile("cp.async.commit_group;\n" ::: "memory")
#define CP_WAIT1()  asm volatile("cp.async.wait_group 1;\n" ::: "memory")
#define LDSM4(r0, r1, r2, r3, addr) \
    asm volatile("ldmatrix.sync.aligned.m8n8.x4.shared.b16 {%0,%1,%2,%3}, [%4];" \
                 : "=r"(r0), "=r"(r1), "=r"(r2), "=r"(r3) : "r"(addr))

__device__ __forceinline__ uint8_t to_e4m3(float f) {
    return (uint8_t)__nv_cvt_float_to_fp8(f, __NV_SATFINITE, __NV_E4M3);
}
__device__ __forceinline__ float from_e4m3(uint8_t s) {
    return __half2float(__nv_cvt_fp8_to_halfraw((__nv_fp8_storage_t)s, __NV_E4M3));
}

// ---------------- prep ----------------
__global__ void prep_kernel(const float* __restrict__ ref, const float* __restrict__ ws,
                            const float* __restrict__ wb, const float* __restrict__ cm) {
    int t = blockIdx.x * 256 + threadIdx.x;
    if (t < NN) {
        g_col[t * 3 + 0] = ref[t * 3 + 0] * 8.0f;
        g_col[t * 3 + 1] = ref[t * 3 + 1] * 8.0f;
        g_col[t * 3 + 2] = ref[t * 3 + 2] * 8.0f;
    }
    if (t < HH * HH) {
        int a = t / HH, b = t % HH;
        float d = (float)(a - b);
        g_G[t] = __expf(-0.5f * d * d / 9.0f);   // theta_gamma = 3
    }
    if (t < CC * CC) {
        g_Ws[t] = cm[t] * ws[t % CC];
        g_Wb[t] = cm[t] * wb[t % CC];
    }
}

// ---------------- build bilateral kernel matrix (fp8, once) ----------------
// exp(-0.5*d2) rounds to e4m3 zero when d2 > 13.86; skipping expf there is exact.
__global__ void build_k_kernel() {
    int jq = blockIdx.x * 128 + threadIdx.x;   // quad of columns
    int j0 = jq * 4;
    int i0 = blockIdx.y * 16;
    float yj = (float)(j0 / WW), xj = (float)(j0 % WW);  // quad within one row
    float cr[4], cg[4], cb[4];
#pragma unroll
    for (int t = 0; t < 4; t++) {
        cr[t] = g_col[(j0 + t) * 3 + 0];
        cg[t] = g_col[(j0 + t) * 3 + 1];
        cb[t] = g_col[(j0 + t) * 3 + 2];
    }
#pragma unroll 2
    for (int t = 0; t < 16; t++) {
        int i = i0 + t;
        float yi = (float)(i / WW), xi = (float)(i % WW);
        float ri = g_col[i * 3 + 0], gi = g_col[i * 3 + 1], bi = g_col[i * 3 + 2];
        float dy = yi - yj;
        float d2v[4];
        bool nearv = false;
#pragma unroll
        for (int s = 0; s < 4; s++) {
            float dx = xi - (xj + (float)s);
            float d2 = (dy * dy + dx * dx) * (1.0f / 64.0f);
            float dr = ri - cr[s], dg = gi - cg[s], db = bi - cb[s];
            d2 += dr * dr + dg * dg + db * db;
            d2v[s] = d2;
            nearv |= (d2 < 13.86f);
        }
        uint32_t packed = 0;
        if (__ballot_sync(0xffffffffu, nearv)) {   // whole warp far -> skip all MUFU
            if (nearv) {
#pragma unroll
                for (int s = 0; s < 4; s++) {
                    float e = (d2v[s] < 13.86f) ? __expf(-0.5f * d2v[s]) : 0.0f;
                    packed |= (uint32_t)to_e4m3(e) << (8 * s);
                }
            }
        }
        *reinterpret_cast<uint32_t*>(&g_K8[(size_t)i * NN + j0]) = packed;
    }
}

// ---------------- prob emission (shared by softmax0 and update) ----------------
__device__ __forceinline__ void emit_probs(const float* v, int n) {
    float mx = -1e30f;
#pragma unroll
    for (int c = 0; c < CC; c++) mx = fmaxf(mx, v[c]);
    float s = 0.0f;
    float e[CC];
#pragma unroll
    for (int c = 0; c < CC; c++) { e[c] = __expf(v[c] - mx); s += e[c]; }
    float inv = 1.0f / s;
#pragma unroll
    for (int c = 0; c < CC; c++) {
        float p = e[c] * inv;
        g_pT[c * NN + n] = __float2half_rn(p);
        uint8_t hi = to_e4m3(p);
        float res = 64.0f * (p - from_e4m3(hi));
        g_pT8[c * NN + n] = hi;
        g_pT8[(CP + c) * NN + n] = to_e4m3(res);
    }
#pragma unroll
    for (int c = CC; c < CP; c++) {
        g_pT8[c * NN + n] = 0;
        g_pT8[(CP + c) * NN + n] = 0;
    }
}

__global__ void softmax0_kernel(const float* __restrict__ u) {
    int n = blockIdx.x * 256 + threadIdx.x;
    float v[CC];
#pragma unroll
    for (int c = 0; c < CC; c++) v[c] = u[n * CC + c];
    emit_probs(v, n);
}

// ---------------- separable spatial filtering ----------------
// G(d) < 2e-22 for |d| >= 30: dropped terms are below 1 ulp of the fp32 sums.
__global__ void conv_x_kernel() {   // grid = 96 (y), block = 288 (x + 96*cg), cg: 7 ch each
    __shared__ float sp[CC * WW];
    int y = blockIdx.x;
    int tid = threadIdx.x;
    for (int t = tid; t < CC * WW; t += 288)
        sp[t] = __half2float(g_pT[(t / WW) * NN + y * WW + (t % WW)]);
    __syncthreads();
    int x = tid % 96, cg = tid / 96;
    int c0 = cg * 7;
    int lo = max(0, x - 29), hi = min(WW, x + 30);
    float acc[7];
#pragma unroll
    for (int i = 0; i < 7; i++) acc[i] = 0.0f;
#pragma unroll 4
    for (int xp = lo; xp < hi; xp++) {
        float g = g_G[xp * WW + x];
#pragma unroll
        for (int i = 0; i < 7; i++) acc[i] += g * sp[(c0 + i) * WW + xp];
    }
#pragma unroll
    for (int i = 0; i < 7; i++)
        g_tmp[(c0 + i) * NN + y * WW + x] = acc[i];
}

__global__ void conv_y_kernel() {   // grid = (12 ytile, 21 c), block = 96 (x)
    __shared__ float gsh[8][HH];
    int c = blockIdx.y, y0 = blockIdx.x * 8, x = threadIdx.x;
    for (int t = threadIdx.x; t < 8 * HH; t += 96)
        gsh[t / HH][t % HH] = g_G[(y0 + t / HH) * HH + (t % HH)];
    __syncthreads();
    float acc[8];
#pragma unroll
    for (int i = 0; i < 8; i++) acc[i] = 0.0f;
    const float* tp = g_tmp + c * NN + x;
    int lo = max(0, y0 - 29), hi = min(HH, y0 + 7 + 30);
#pragma unroll 4
    for (int yp = lo; yp < hi; yp++) {
        float v = tp[yp * WW];
#pragma unroll
        for (int i = 0; i < 8; i++) acc[i] += gsh[i][yp] * v;
    }
#pragma unroll
    for (int i = 0; i < 8; i++)
        g_S[c * NN + (y0 + i) * WW + x] = acc[i];
}

// ---------------- fp8 GEMM: banded, Bp = K8 @ pT8^T (hi & lo), m32 warp tiles ----------------
__device__ __forceinline__ void mma_fp8(float* d, uint32_t a0, uint32_t a1, uint32_t a2,
                                        uint32_t a3, uint32_t b0, uint32_t b1) {
    asm volatile(
        "mma.sync.aligned.m16n8k32.row.col.f32.e4m3.e4m3.f32 "
        "{%0,%1,%2,%3},{%4,%5,%6,%7},{%8,%9},{%0,%1,%2,%3};\n"
        : "+f"(d[0]), "+f"(d[1]), "+f"(d[2]), "+f"(d[3])
        : "r"(a0), "r"(a1), "r"(a2), "r"(a3), "r"(b0), "r"(b1));
}

__global__ void __launch_bounds__(128, 2) gemm_kernel() {
    // grid = (72, KSPLIT). Block: 128 rows; k-window clipped to the exact-zero band
    // |y_i - y_j| <= 30 (K entries outside are exactly 0 in e4m3), split 4 ways.
    __shared__ __align__(16) uint8_t sA[3 * SA_BUF];   // 49152 B
    __shared__ __align__(16) uint8_t sB[3 * SB_BUF];   // 18432 B
    int tid = threadIdx.x;
    int warp = tid >> 5, lane = tid & 31;
    int grp = lane >> 2, tig = lane & 3;
    int rowBase = blockIdx.x * RB;

    // banded k-window for this row tile, aligned to KT
    int ya = rowBase / WW;
    int yb = (rowBase + RB - 1) / WW;
    int jlo = (max(0, (ya - 30) * WW)) & ~(KT - 1);
    int jhi = min(NN, ((yb + 31) * WW + KT - 1) & ~(KT - 1));
    int len = jhi - jlo;
    int chunk = ((len / KSPLIT + KT - 1) / KT) * KT;
    int kstart = jlo + blockIdx.y * chunk;
    int kend = min(jhi, kstart + chunk);
    int NST = (kend > kstart) ? (kend - kstart) / KT : 0;

    uint32_t sA_u = (uint32_t)__cvta_generic_to_shared(&sA[0]);
    uint32_t sB_u = (uint32_t)__cvta_generic_to_shared(&sB[0]);

    auto prefetch = [&](int s, int buf) {
        if (s >= NST) return;
        size_t kbase = (size_t)kstart + (size_t)s * KT;
#pragma unroll
        for (int i = 0; i < 8; i++) {            // 1024 chunks of 16B for A (128 rows)
            int chunkid = tid + i * 128;
            int r = chunkid >> 3, c = chunkid & 7;
            const uint8_t* src = g_K8 + (size_t)(rowBase + r) * NN + kbase + c * 16;
            uint32_t dst = sA_u + buf * SA_BUF + r * 128 + ((c ^ (r & 7)) << 4);
            CP_ASYNC16(dst, src);
        }
#pragma unroll
        for (int i = 0; i < 3; i++) {            // 384 chunks for B (48 rows)
            int chunkid = tid + i * 128;
            int r = chunkid >> 3, c = chunkid & 7;
            const uint8_t* src = g_pT8 + (size_t)r * NN + kbase + c * 16;
            uint32_t dst = sB_u + buf * SB_BUF + r * 128 + ((c ^ (r & 7)) << 4);
            CP_ASYNC16(dst, src);
        }
    };

    float d[2][6][4];
#pragma unroll
    for (int m = 0; m < 2; m++)
#pragma unroll
        for (int i = 0; i < 6; i++)
#pragma unroll
            for (int j = 0; j < 4; j++) d[m][i][j] = 0.0f;

    prefetch(0, 0); CP_COMMIT();
    prefetch(1, 1); CP_COMMIT();

    // ---- ldmatrix address setup (loop-invariant) ----
    int l7 = lane & 7;
    int aHalf = lane >> 4;
    int bHalf = (lane >> 3) & 1;
    uint32_t aBase[2];
#pragma unroll
    for (int m = 0; m < 2; m++) {
        int aRow = warp * 32 + m * 16 + ((lane >> 3) & 1) * 8 + l7;
        aBase[m] = sA_u + (uint32_t)aRow * 128;
    }
    uint32_t bBase[3];
#pragma unroll
    for (int p = 0; p < 3; p++)
        bBase[p] = sB_u + (uint32_t)(((2 * p + (lane >> 4)) * 8 + l7) * 128);
    int offA[4], offB[4];
#pragma unroll
    for (int kk = 0; kk < 4; kk++) {
        offA[kk] = (((2 * kk + aHalf) ^ l7) << 4);
        offB[kk] = (((2 * kk + bHalf) ^ l7) << 4);
    }

    int buf = 0;
    for (int s = 0; s < NST; s++) {
        CP_WAIT1();
        __syncthreads();
        prefetch(s + 2, (s + 2) % 3);
        CP_COMMIT();
        uint32_t A0 = aBase[0] + buf * SA_BUF;
        uint32_t A1 = aBase[1] + buf * SA_BUF;
        uint32_t B0 = bBase[0] + buf * SB_BUF;
        uint32_t B1 = bBase[1] + buf * SB_BUF;
        uint32_t B2 = bBase[2] + buf * SB_BUF;
        buf = (buf == 2) ? 0 : buf + 1;
#pragma unroll
        for (int kk = 0; kk < 4; kk++) {
            uint32_t a00, a01, a02, a03, a10, a11, a12, a13;
            LDSM4(a00, a01, a02, a03, A0 + offA[kk]);
            LDSM4(a10, a11, a12, a13, A1 + offA[kk]);
            uint32_t b00, b01, b10, b11;
            LDSM4(b00, b01, b10, b11, B0 + offB[kk]);
            uint32_t b20, b21, b30, b31;
            LDSM4(b20, b21, b30, b31, B1 + offB[kk]);
            uint32_t b40, b41, b50, b51;
            LDSM4(b40, b41, b50, b51, B2 + offB[kk]);
            mma_fp8(d[0][0], a00, a01, a02, a03, b00, b01);
            mma_fp8(d[0][1], a00, a01, a02, a03, b10, b11);
            mma_fp8(d[0][2], a00, a01, a02, a03, b20, b21);
            mma_fp8(d[0][3], a00, a01, a02, a03, b30, b31);
            mma_fp8(d[0][4], a00, a01, a02, a03, b40, b41);
            mma_fp8(d[0][5], a00, a01, a02, a03, b50, b51);
            mma_fp8(d[1][0], a10, a11, a12, a13, b00, b01);
            mma_fp8(d[1][1], a10, a11, a12, a13, b10, b11);
            mma_fp8(d[1][2], a10, a11, a12, a13, b20, b21);
            mma_fp8(d[1][3], a10, a11, a12, a13, b30, b31);
            mma_fp8(d[1][4], a10, a11, a12, a13, b40, b41);
            mma_fp8(d[1][5], a10, a11, a12, a13, b50, b51);
        }
    }

    float* outp = g_Bp[blockIdx.y];
#pragma unroll
    for (int m = 0; m < 2; m++) {
        int row0 = rowBase + warp * 32 + m * 16 + grp;
#pragma unroll
        for (int nt = 0; nt < 3; nt++) {   // combine hi + lo/64
            int col = nt * 8 + 2 * tig;
            float v00 = d[m][nt][0] + d[m][nt + 3][0] * (1.0f / 64.0f);
            float v01 = d[m][nt][1] + d[m][nt + 3][1] * (1.0f / 64.0f);
            float v10 = d[m][nt][2] + d[m][nt + 3][2] * (1.0f / 64.0f);
            float v11 = d[m][nt][3] + d[m][nt + 3][3] * (1.0f / 64.0f);
            *reinterpret_cast<float2*>(&outp[(size_t)row0 * CP + col]) = make_float2(v00, v01);
            *reinterpret_cast<float2*>(&outp[(size_t)(row0 + 8) * CP + col]) = make_float2(v10, v11);
        }
    }
}

// ---------------- fused update + softmax: q = u - S@Ws^T - B@Wb^T, then probs ----------------
__global__ void update_kernel(const float* __restrict__ u, float* __restrict__ outp, int last) {
    __shared__ float su[256 * CC];
    __shared__ float sws[CC * CC], swb[CC * CC];
    int tid = threadIdx.x;
    for (int t = tid; t < CC * CC; t += 256) { sws[t] = g_Ws[t]; swb[t] = g_Wb[t]; }
    int base = blockIdx.x * 256 * CC;
    for (int t = tid; t < 256 * CC; t += 256) su[t] = u[base + t];
    __syncthreads();
    int n = blockIdx.x * 256 + tid;

    float sv[CC], bv[CP];
#pragma unroll
    for (int c = 0; c < CC; c++) sv[c] = g_S[c * NN + n];
#pragma unroll
    for (int q4 = 0; q4 < 6; q4++) {
        float4 a = *reinterpret_cast<const float4*>(&g_Bp[0][(size_t)n * CP + q4 * 4]);
        float4 b = *reinterpret_cast<const float4*>(&g_Bp[1][(size_t)n * CP + q4 * 4]);
        float4 cc4 = *reinterpret_cast<const float4*>(&g_Bp[2][(size_t)n * CP + q4 * 4]);
        float4 e = *reinterpret_cast<const float4*>(&g_Bp[3][(size_t)n * CP + q4 * 4]);
        bv[q4 * 4 + 0] = a.x + b.x + cc4.x + e.x;
        bv[q4 * 4 + 1] = a.y + b.y + cc4.y + e.y;
        bv[q4 * 4 + 2] = a.z + b.z + cc4.z + e.z;
        bv[q4 * 4 + 3] = a.w + b.w + cc4.w + e.w;
    }

    float qn[CC];
#pragma unroll
    for (int k = 0; k < CC; k++) {
        float acc = 0.0f;
#pragma unroll
        for (int c = 0; c < CC; c++)
            acc += sws[k * CC + c] * sv[c] + swb[k * CC + c] * bv[c];
        qn[k] = su[tid * CC + k] - acc;
    }

    if (last) {
#pragma unroll
        for (int k = 0; k < CC; k++) outp[n * CC + k] = qn[k];
    } else {
        emit_probs(qn, n);
    }
}

// ---------------- launch: fork-join DAG (convs overlap gemm; softmax0+convs overlap build_k) --
extern "C" void kernel_launch(void* const* d_in, const int* in_sizes, int n_in,
                              void* d_out, int out_size) {
    const float* u   = (const float*)d_in[0];
    const float* ref = (const float*)d_in[1];
    const float* ws  = (const float*)d_in[2];
    const float* wb  = (const float*)d_in[3];
    const float* cm  = (const float*)d_in[4];
    float* out = (float*)d_out;

    static cudaStream_t s2 = nullptr;
    static cudaEvent_t eFork = nullptr, eEmit = nullptr, eConv = nullptr;
    if (s2 == nullptr) {
        cudaStreamCreateWithFlags(&s2, cudaStreamNonBlocking);
        cudaEventCreateWithFlags(&eFork, cudaEventDisableTiming);
        cudaEventCreateWithFlags(&eEmit, cudaEventDisableTiming);
        cudaEventCreateWithFlags(&eConv, cudaEventDisableTiming);
    }

    // fork side stream off the main (legacy) stream
    cudaEventRecord(eFork, 0);
    cudaStreamWaitEvent(s2, eFork, 0);

    // main: prep -> build_K (long). side: softmax0 -> convs (independent of K).
    prep_kernel<<<36, 256>>>(ref, ws, wb, cm);
    build_k_kernel<<<dim3(18, 576), 128>>>();

    softmax0_kernel<<<36, 256, 0, s2>>>(u);
    cudaEventRecord(eEmit, s2);      // probs ready (iteration 0)

    for (int it = 0; it < 5; it++) {
        if (it > 0) cudaStreamWaitEvent(s2, eEmit, 0);
        conv_x_kernel<<<96, 288, 0, s2>>>();
        conv_y_kernel<<<dim3(12, 21), 96, 0, s2>>>();
        cudaEventRecord(eConv, s2);

        if (it == 0) cudaStreamWaitEvent(0, eEmit, 0);  // gemm needs softmax0
        gemm_kernel<<<dim3(72, KSPLIT), 128>>>();

        cudaStreamWaitEvent(0, eConv, 0);                // update needs convs
        update_kernel<<<36, 256>>>(u, out, it == 4 ? 1 : 0);
        if (it < 4) cudaEventRecord(eEmit, 0);           // new probs for next iter
    }
}

// round 8
// speedup vs baseline: 7.7085x; 1.0247x over previous
#include <cuda_runtime.h>
#include <cuda_fp16.h>
#include <cuda_fp8.h>
#include <cstdint>

#define HH 96
#define WW 96
#define CC 21
#define NN 9216          // HH*WW
#define CP 24            // padded channel count
#define BROWS 48         // B operand rows: 24 hi + 24 lo (residual)

#define KT 128           // k-tile (fp8 elements = bytes)
#define RB 128           // rows per gemm block (4 warps x m32)
#define NTILES (NN / RB)      // 72 row tiles
#define KB_W 6656             // banded storage width (>= max window len 6272)
#define KSPLIT 4
#define SA_BUF (RB * 128)     // 16384 B per stage
#define SB_BUF (BROWS * 128)  // 6144 B per stage

// ---------------- scratch (device globals; no allocation allowed) ----------------
__device__ uint8_t g_Kb[(size_t)NTILES * RB * KB_W];  // banded bilateral kernel, e4m3, ~61MB
__device__ __half  g_pT[CC * NN];           // probs planar [c][n], fp16 (conv path)
__device__ uint8_t g_pT8[BROWS * NN];       // probs e4m3 planar: rows 0-23 hi, 24-47 lo*64
__device__ float   g_tmp[CC * NN];          // conv intermediate, planar
__device__ float   g_S[CC * NN];            // spatial message, planar
__device__ float   g_Bp[KSPLIT][NN * CP];   // bilateral partials per k-split
__device__ float   g_G[HH * HH];            // 1D spatial gaussian G[a][b]
__device__ float   g_Ws[CC * CC];           // compat[k][c] * ws[c]
__device__ float   g_Wb[CC * CC];           // compat[k][c] * wb[c]
__device__ float   g_col[NN * 3];           // colors * 8 (= /theta_beta)

// banded window for a row tile (identical formula in build and gemm)
__device__ __forceinline__ void tile_window(int tile, int& jlo, int& jhi) {
    int rowBase = tile * RB;
    int ya = rowBase / WW;
    int yb = (rowBase + RB - 1) / WW;
    jlo = max(0, (ya - 30) * WW) & ~(KT - 1);
    jhi = min(NN, ((yb + 31) * WW + KT - 1) & ~(KT - 1));
}

// ---------------- async / ldmatrix helpers ----------------
#define CP_ASYNC16(dst, src) \
    asm volatile("cp.async.cg.shared.global [%0], [%1], 16;\n" :: "r"(dst), "l"(src))
#define CP_COMMIT() asm volatile("cp.async.commit_group;\n" ::: "memory")
#define CP_WAIT1()  asm volatile("cp.async.wait_group 1;\n" ::: "memory")
#define LDSM4(r0, r1, r2, r3, addr) \
    asm volatile("ldmatrix.sync.aligned.m8n8.x4.shared.b16 {%0,%1,%2,%3}, [%4];" \
                 : "=r"(r0), "=r"(r1), "=r"(r2), "=r"(r3) : "r"(addr))

__device__ __forceinline__ uint8_t to_e4m3(float f) {
    return (uint8_t)__nv_cvt_float_to_fp8(f, __NV_SATFINITE, __NV_E4M3);
}
__device__ __forceinline__ float from_e4m3(uint8_t s) {
    return __half2float(__nv_cvt_fp8_to_halfraw((__nv_fp8_storage_t)s, __NV_E4M3));
}

// ---------------- prep ----------------
__global__ void prep_kernel(const float* __restrict__ ref, const float* __restrict__ ws,
                            const float* __restrict__ wb, const float* __restrict__ cm) {
    int t = blockIdx.x * 256 + threadIdx.x;
    if (t < NN) {
        g_col[t * 3 + 0] = ref[t * 3 + 0] * 8.0f;
        g_col[t * 3 + 1] = ref[t * 3 + 1] * 8.0f;
        g_col[t * 3 + 2] = ref[t * 3 + 2] * 8.0f;
    }
    if (t < HH * HH) {
        int a = t / HH, b = t % HH;
        float d = (float)(a - b);
        g_G[t] = __expf(-0.5f * d * d / 9.0f);   // theta_gamma = 3
    }
    if (t < CC * CC) {
        g_Ws[t] = cm[t] * ws[t % CC];
        g_Wb[t] = cm[t] * wb[t % CC];
    }
}

// ---------------- build banded bilateral kernel (fp8, once) ----------------
// exp(-0.5*d2) rounds to e4m3 zero when d2 > 13.86; skipping expf there is exact.
// Only the |dy|<=30 window (plus alignment slack) is ever read -> only it is built.
__global__ void build_k_kernel() {
    int tile = blockIdx.y >> 3;
    int i0 = tile * RB + (blockIdx.y & 7) * 16;
    int jlo, jhi;
    tile_window(tile, jlo, jhi);
    int kcol = (blockIdx.x * 128 + threadIdx.x) * 4;
    int j0 = jlo + kcol;
    if (j0 >= jhi) return;                     // padding beyond window: never read
    float yj = (float)(j0 / WW), xj = (float)(j0 % WW);  // quad within one row (WW%4==0)
    float cr[4], cg[4], cb[4];
#pragma unroll
    for (int t = 0; t < 4; t++) {
        cr[t] = g_col[(j0 + t) * 3 + 0];
        cg[t] = g_col[(j0 + t) * 3 + 1];
        cb[t] = g_col[(j0 + t) * 3 + 2];
    }
    uint8_t* dst0 = g_Kb + (size_t)i0 * KB_W + kcol;
#pragma unroll 2
    for (int t = 0; t < 16; t++) {
        int i = i0 + t;
        float yi = (float)(i / WW), xi = (float)(i % WW);
        float ri = g_col[i * 3 + 0], gi = g_col[i * 3 + 1], bi = g_col[i * 3 + 2];
        float dy = yi - yj;
        float d2v[4];
        bool nearv = false;
#pragma unroll
        for (int s = 0; s < 4; s++) {
            float dx = xi - (xj + (float)s);
            float d2 = (dy * dy + dx * dx) * (1.0f / 64.0f);
            float dr = ri - cr[s], dg = gi - cg[s], db = bi - cb[s];
            d2 += dr * dr + dg * dg + db * db;
            d2v[s] = d2;
            nearv |= (d2 < 13.86f);
        }
        uint32_t packed = 0;
        if (__ballot_sync(0xffffffffu, nearv)) {   // whole warp far -> skip all MUFU
            if (nearv) {
#pragma unroll
                for (int s = 0; s < 4; s++) {
                    float e = (d2v[s] < 13.86f) ? __expf(-0.5f * d2v[s]) : 0.0f;
                    packed |= (uint32_t)to_e4m3(e) << (8 * s);
                }
            }
        }
        *reinterpret_cast<uint32_t*>(dst0 + (size_t)t * KB_W) = packed;
    }
}

// ---------------- prob emission (shared by softmax0 and update) ----------------
__device__ __forceinline__ void emit_probs(const float* v, int n) {
    float mx = -1e30f;
#pragma unroll
    for (int c = 0; c < CC; c++) mx = fmaxf(mx, v[c]);
    float s = 0.0f;
    float e[CC];
#pragma unroll
    for (int c = 0; c < CC; c++) { e[c] = __expf(v[c] - mx); s += e[c]; }
    float inv = 1.0f / s;
#pragma unroll
    for (int c = 0; c < CC; c++) {
        float p = e[c] * inv;
        g_pT[c * NN + n] = __float2half_rn(p);
        uint8_t hi = to_e4m3(p);
        float res = 64.0f * (p - from_e4m3(hi));
        g_pT8[c * NN + n] = hi;
        g_pT8[(CP + c) * NN + n] = to_e4m3(res);
    }
#pragma unroll
    for (int c = CC; c < CP; c++) {
        g_pT8[c * NN + n] = 0;
        g_pT8[(CP + c) * NN + n] = 0;
    }
}

__global__ void softmax0_kernel(const float* __restrict__ u) {
    int n = blockIdx.x * 256 + threadIdx.x;
    float v[CC];
#pragma unroll
    for (int c = 0; c < CC; c++) v[c] = u[n * CC + c];
    emit_probs(v, n);
}

// ---------------- separable spatial filtering ----------------
// G(d) < 2e-22 for |d| >= 30: dropped terms are below 1 ulp of the fp32 sums.
__global__ void conv_x_kernel() {   // grid = (96 y, 7 cg), block = 288 (96 x * 3 ch)
    __shared__ float sp[3][WW];
    int y = blockIdx.x;
    int tid = threadIdx.x;
    int sub = tid / 96, x = tid % 96;
    int c = blockIdx.y * 3 + sub;
    sp[sub][x] = __half2float(g_pT[c * NN + y * WW + x]);
    __syncthreads();
    int lo = max(0, x - 29), hi = min(WW, x + 30);
    float a0 = 0.f, a1 = 0.f;
    int xp = lo;
    for (; xp + 2 <= hi; xp += 2) {
        a0 += g_G[xp * WW + x] * sp[sub][xp];
        a1 += g_G[(xp + 1) * WW + x] * sp[sub][xp + 1];
    }
    if (xp < hi) a0 += g_G[xp * WW + x] * sp[sub][xp];
    g_tmp[c * NN + y * WW + x] = a0 + a1;
}

__global__ void conv_y_kernel() {   // grid = (12 ytile, 21 c), block = 96 (x)
    __shared__ float gsh[8][HH];
    int c = blockIdx.y, y0 = blockIdx.x * 8, x = threadIdx.x;
    for (int t = threadIdx.x; t < 8 * HH; t += 96)
        gsh[t / HH][t % HH] = g_G[(y0 + t / HH) * HH + (t % HH)];
    __syncthreads();
    float acc[8];
#pragma unroll
    for (int i = 0; i < 8; i++) acc[i] = 0.0f;
    const float* tp = g_tmp + c * NN + x;
    int lo = max(0, y0 - 29), hi = min(HH, y0 + 7 + 30);
#pragma unroll 4
    for (int yp = lo; yp < hi; yp++) {
        float v = tp[yp * WW];
#pragma unroll
        for (int i = 0; i < 8; i++) acc[i] += gsh[i][yp] * v;
    }
#pragma unroll
    for (int i = 0; i < 8; i++)
        g_S[c * NN + (y0 + i) * WW + x] = acc[i];
}

// ---------------- fp8 GEMM: banded, Bp = Kb @ pT8^T (hi & lo), m32 warp tiles ----------------
__device__ __forceinline__ void mma_fp8(float* d, uint32_t a0, uint32_t a1, uint32_t a2,
                                        uint32_t a3, uint32_t b0, uint32_t b1) {
    asm volatile(
        "mma.sync.aligned.m16n8k32.row.col.f32.e4m3.e4m3.f32 "
        "{%0,%1,%2,%3},{%4,%5,%6,%7},{%8,%9},{%0,%1,%2,%3};\n"
        : "+f"(d[0]), "+f"(d[1]), "+f"(d[2]), "+f"(d[3])
        : "r"(a0), "r"(a1), "r"(a2), "r"(a3), "r"(b0), "r"(b1));
}

__global__ void __launch_bounds__(128, 2) gemm_kernel() {
    // grid = (72, KSPLIT). Block: 128 rows; banded k-window split KSPLIT ways.
    __shared__ __align__(16) uint8_t sA[3 * SA_BUF];   // 49152 B
    __shared__ __align__(16) uint8_t sB[3 * SB_BUF];   // 18432 B
    int tid = threadIdx.x;
    int warp = tid >> 5, lane = tid & 31;
    int grp = lane >> 2, tig = lane & 3;
    int tile = blockIdx.x;
    int rowBase = tile * RB;

    int jlo, jhi;
    tile_window(tile, jlo, jhi);
    int len = jhi - jlo;
    int chunk = ((len / KSPLIT + KT - 1) / KT) * KT;
    int kstartRel = blockIdx.y * chunk;
    int kendRel = min(len, kstartRel + chunk);
    int NST = (kendRel > kstartRel) ? (kendRel - kstartRel) / KT : 0;

    const uint8_t* Arow0 = g_Kb + (size_t)rowBase * KB_W + kstartRel;
    const uint8_t* Bbase = g_pT8 + jlo + kstartRel;

    uint32_t sA_u = (uint32_t)__cvta_generic_to_shared(&sA[0]);
    uint32_t sB_u = (uint32_t)__cvta_generic_to_shared(&sB[0]);

    auto prefetch = [&](int s, int buf) {
        if (s >= NST) return;
        size_t kbase = (size_t)s * KT;
#pragma unroll
        for (int i = 0; i < 8; i++) {            // 1024 chunks of 16B for A (128 rows)
            int chunkid = tid + i * 128;
            int r = chunkid >> 3, c = chunkid & 7;
            const uint8_t* src = Arow0 + (size_t)r * KB_W + kbase + c * 16;
            uint32_t dst = sA_u + buf * SA_BUF + r * 128 + ((c ^ (r & 7)) << 4);
            CP_ASYNC16(dst, src);
        }
#pragma unroll
        for (int i = 0; i < 3; i++) {            // 384 chunks for B (48 rows)
            int chunkid = tid + i * 128;
            int r = chunkid >> 3, c = chunkid & 7;
            const uint8_t* src = Bbase + (size_t)r * NN + kbase + c * 16;
            uint32_t dst = sB_u + buf * SB_BUF + r * 128 + ((c ^ (r & 7)) << 4);
            CP_ASYNC16(dst, src);
        }
    };

    float d[2][6][4];
#pragma unroll
    for (int m = 0; m < 2; m++)
#pragma unroll
        for (int i = 0; i < 6; i++)
#pragma unroll
            for (int j = 0; j < 4; j++) d[m][i][j] = 0.0f;

    prefetch(0, 0); CP_COMMIT();
    prefetch(1, 1); CP_COMMIT();

    // ---- ldmatrix address setup (loop-invariant) ----
    int l7 = lane & 7;
    int aHalf = lane >> 4;
    int bHalf = (lane >> 3) & 1;
    uint32_t aBase[2];
#pragma unroll
    for (int m = 0; m < 2; m++) {
        int aRow = warp * 32 + m * 16 + ((lane >> 3) & 1) * 8 + l7;
        aBase[m] = sA_u + (uint32_t)aRow * 128;
    }
    uint32_t bBase[3];
#pragma unroll
    for (int p = 0; p < 3; p++)
        bBase[p] = sB_u + (uint32_t)(((2 * p + (lane >> 4)) * 8 + l7) * 128);
    int offA[4], offB[4];
#pragma unroll
    for (int kk = 0; kk < 4; kk++) {
        offA[kk] = (((2 * kk + aHalf) ^ l7) << 4);
        offB[kk] = (((2 * kk + bHalf) ^ l7) << 4);
    }

    int buf = 0;
    for (int s = 0; s < NST; s++) {
        CP_WAIT1();
        __syncthreads();
        prefetch(s + 2, (s + 2) % 3);
        CP_COMMIT();
        uint32_t A0 = aBase[0] + buf * SA_BUF;
        uint32_t A1 = aBase[1] + buf * SA_BUF;
        uint32_t B0 = bBase[0] + buf * SB_BUF;
        uint32_t B1 = bBase[1] + buf * SB_BUF;
        uint32_t B2 = bBase[2] + buf * SB_BUF;
        buf = (buf == 2) ? 0 : buf + 1;
#pragma unroll
        for (int kk = 0; kk < 4; kk++) {
            uint32_t a00, a01, a02, a03, a10, a11, a12, a13;
            LDSM4(a00, a01, a02, a03, A0 + offA[kk]);
            LDSM4(a10, a11, a12, a13, A1 + offA[kk]);
            uint32_t b00, b01, b10, b11;
            LDSM4(b00, b01, b10, b11, B0 + offB[kk]);
            uint32_t b20, b21, b30, b31;
            LDSM4(b20, b21, b30, b31, B1 + offB[kk]);
            uint32_t b40, b41, b50, b51;
            LDSM4(b40, b41, b50, b51, B2 + offB[kk]);
            mma_fp8(d[0][0], a00, a01, a02, a03, b00, b01);
            mma_fp8(d[0][1], a00, a01, a02, a03, b10, b11);
            mma_fp8(d[0][2], a00, a01, a02, a03, b20, b21);
            mma_fp8(d[0][3], a00, a01, a02, a03, b30, b31);
            mma_fp8(d[0][4], a00, a01, a02, a03, b40, b41);
            mma_fp8(d[0][5], a00, a01, a02, a03, b50, b51);
            mma_fp8(d[1][0], a10, a11, a12, a13, b00, b01);
            mma_fp8(d[1][1], a10, a11, a12, a13, b10, b11);
            mma_fp8(d[1][2], a10, a11, a12, a13, b20, b21);
            mma_fp8(d[1][3], a10, a11, a12, a13, b30, b31);
            mma_fp8(d[1][4], a10, a11, a12, a13, b40, b41);
            mma_fp8(d[1][5], a10, a11, a12, a13, b50, b51);
        }
    }

    float* outp = g_Bp[blockIdx.y];
#pragma unroll
    for (int m = 0; m < 2; m++) {
        int row0 = rowBase + warp * 32 + m * 16 + grp;
#pragma unroll
        for (int nt = 0; nt < 3; nt++) {   // combine hi + lo/64
            int col = nt * 8 + 2 * tig;
            float v00 = d[m][nt][0] + d[m][nt + 3][0] * (1.0f / 64.0f);
            float v01 = d[m][nt][1] + d[m][nt + 3][1] * (1.0f / 64.0f);
            float v10 = d[m][nt][2] + d[m][nt + 3][2] * (1.0f / 64.0f);
            float v11 = d[m][nt][3] + d[m][nt + 3][3] * (1.0f / 64.0f);
            *reinterpret_cast<float2*>(&outp[(size_t)row0 * CP + col]) = make_float2(v00, v01);
            *reinterpret_cast<float2*>(&outp[(size_t)(row0 + 8) * CP + col]) = make_float2(v10, v11);
        }
    }
}

// ---------------- fused update + softmax: q = u - S@Ws^T - B@Wb^T, then probs ----------------
__global__ void update_kernel(const float* __restrict__ u, float* __restrict__ outp, int last) {
    __shared__ float su[256 * CC];
    __shared__ float sws[CC * CC], swb[CC * CC];
    int tid = threadIdx.x;
    for (int t = tid; t < CC * CC; t += 256) { sws[t] = g_Ws[t]; swb[t] = g_Wb[t]; }
    int base = blockIdx.x * 256 * CC;
    for (int t = tid; t < 256 * CC; t += 256) su[t] = u[base + t];
    __syncthreads();
    int n = blockIdx.x * 256 + tid;

    float sv[CC], bv[CP];
#pragma unroll
    for (int c = 0; c < CC; c++) sv[c] = g_S[c * NN + n];
#pragma unroll
    for (int q4 = 0; q4 < 6; q4++) {
        float4 a = *reinterpret_cast<const float4*>(&g_Bp[0][(size_t)n * CP + q4 * 4]);
        float4 b = *reinterpret_cast<const float4*>(&g_Bp[1][(size_t)n * CP + q4 * 4]);
        float4 cc4 = *reinterpret_cast<const float4*>(&g_Bp[2][(size_t)n * CP + q4 * 4]);
        float4 e = *reinterpret_cast<const float4*>(&g_Bp[3][(size_t)n * CP + q4 * 4]);
        bv[q4 * 4 + 0] = a.x + b.x + cc4.x + e.x;
        bv[q4 * 4 + 1] = a.y + b.y + cc4.y + e.y;
        bv[q4 * 4 + 2] = a.z + b.z + cc4.z + e.z;
        bv[q4 * 4 + 3] = a.w + b.w + cc4.w + e.w;
    }

    float qn[CC];
#pragma unroll
    for (int k = 0; k < CC; k++) {
        float acc = 0.0f;
#pragma unroll
        for (int c = 0; c < CC; c++)
            acc += sws[k * CC + c] * sv[c] + swb[k * CC + c] * bv[c];
        qn[k] = su[tid * CC + k] - acc;
    }

    if (last) {
#pragma unroll
        for (int k = 0; k < CC; k++) outp[n * CC + k] = qn[k];
    } else {
        emit_probs(qn, n);
    }
}

// ---------------- launch: fork-join DAG (convs overlap gemm; softmax0+convs overlap build_k) --
extern "C" void kernel_launch(void* const* d_in, const int* in_sizes, int n_in,
                              void* d_out, int out_size) {
    const float* u   = (const float*)d_in[0];
    const float* ref = (const float*)d_in[1];
    const float* ws  = (const float*)d_in[2];
    const float* wb  = (const float*)d_in[3];
    const float* cm  = (const float*)d_in[4];
    float* out = (float*)d_out;

    static cudaStream_t s2 = nullptr;
    static cudaEvent_t eFork = nullptr, eEmit = nullptr, eConv = nullptr;
    if (s2 == nullptr) {
        cudaStreamCreateWithFlags(&s2, cudaStreamNonBlocking);
        cudaEventCreateWithFlags(&eFork, cudaEventDisableTiming);
        cudaEventCreateWithFlags(&eEmit, cudaEventDisableTiming);
        cudaEventCreateWithFlags(&eConv, cudaEventDisableTiming);
    }

    // fork side stream off the main (legacy) stream
    cudaEventRecord(eFork, 0);
    cudaStreamWaitEvent(s2, eFork, 0);

    // main: prep -> build_K (long). side: softmax0 -> convs (independent of K).
    prep_kernel<<<36, 256>>>(ref, ws, wb, cm);
    build_k_kernel<<<dim3(13, 576), 128>>>();

    softmax0_kernel<<<36, 256, 0, s2>>>(u);
    cudaEventRecord(eEmit, s2);      // probs ready (iteration 0)

    for (int it = 0; it < 5; it++) {
        if (it > 0) cudaStreamWaitEvent(s2, eEmit, 0);
        conv_x_kernel<<<dim3(96, 7), 288, 0, s2>>>();
        conv_y_kernel<<<dim3(12, 21), 96, 0, s2>>>();
        cudaEventRecord(eConv, s2);

        if (it == 0) cudaStreamWaitEvent(0, eEmit, 0);  // gemm needs softmax0
        gemm_kernel<<<dim3(NTILES, KSPLIT), 128>>>();

        cudaStreamWaitEvent(0, eConv, 0);                // update needs convs
        update_kernel<<<36, 256>>>(u, out, it == 4 ? 1 : 0);
        if (it < 4) cudaEventRecord(eEmit, 0);           // new probs for next iter
    }
}

// round 9
// speedup vs baseline: 10.2953x; 1.3356x over previous
#include <cuda_runtime.h>
#include <cuda_fp16.h>
#include <cuda_fp8.h>
#include <cstdint>

#define HH 96
#define WW 96
#define CC 21
#define NN 9216          // HH*WW
#define CP 24            // padded channel count
#define BROWS 48         // B operand rows: 24 hi + 24 lo (residual)

#define KT 128           // k-tile (fp8 elements = bytes)
#define RB 128           // rows per gemm block (4 warps x m32)
#define NTILES (NN / RB)      // 72 row tiles
#define KB_W 6656             // banded storage width (>= max window len 6272)
#define KSPLIT 4
#define SA_BUF (RB * 128)     // 16384 B per stage
#define SB_BUF (BROWS * 128)  // 6144 B per stage

#define TMP_ROWS 160          // 96 rows + 29 top halo + 35 bottom pad (zeroed)
#define TMP_PLANE (TMP_ROWS * WW)

// ---------------- scratch (device globals; no allocation allowed) ----------------
__device__ uint8_t g_Kb[(size_t)NTILES * RB * KB_W];  // banded bilateral kernel, e4m3, ~61MB
__device__ __half  g_pT[CC * NN];           // probs planar [c][n], fp16 (conv path)
__device__ uint8_t g_pT8[BROWS * NN];       // probs e4m3 planar: rows 0-23 hi, 24-47 lo*64
__device__ float   g_tmp2[CC * TMP_PLANE];  // conv intermediate, y-haloed planar
__device__ float   g_S[CC * NN];            // spatial message, planar
__device__ float   g_Bp[KSPLIT][NN * CP];   // bilateral partials per k-split
__device__ float   g_tap[64];               // 60 FIR taps exp(-(t-29)^2/18), zero-padded
__device__ float   g_Ws[CC * CC];           // compat[k][c] * ws[c]
__device__ float   g_Wb[CC * CC];           // compat[k][c] * wb[c]
__device__ float   g_col[NN * 3];           // colors * 8 (= /theta_beta)

// banded window for a row tile (identical formula in build and gemm)
__device__ __forceinline__ void tile_window(int tile, int& jlo, int& jhi) {
    int rowBase = tile * RB;
    int ya = rowBase / WW;
    int yb = (rowBase + RB - 1) / WW;
    jlo = max(0, (ya - 30) * WW) & ~(KT - 1);
    jhi = min(NN, ((yb + 31) * WW + KT - 1) & ~(KT - 1));
}

// ---------------- async / ldmatrix helpers ----------------
#define CP_ASYNC16(dst, src) \
    asm volatile("cp.async.cg.shared.global [%0], [%1], 16;\n" :: "r"(dst), "l"(src))
#define CP_COMMIT() asm volatile("cp.async.commit_group;\n" ::: "memory")
#define CP_WAIT1()  asm volatile("cp.async.wait_group 1;\n" ::: "memory")
#define LDSM4(r0, r1, r2, r3, addr) \
    asm volatile("ldmatrix.sync.aligned.m8n8.x4.shared.b16 {%0,%1,%2,%3}, [%4];" \
                 : "=r"(r0), "=r"(r1), "=r"(r2), "=r"(r3) : "r"(addr))

__device__ __forceinline__ uint8_t to_e4m3(float f) {
    return (uint8_t)__nv_cvt_float_to_fp8(f, __NV_SATFINITE, __NV_E4M3);
}
__device__ __forceinline__ float from_e4m3(uint8_t s) {
    return __half2float(__nv_cvt_fp8_to_halfraw((__nv_fp8_storage_t)s, __NV_E4M3));
}

// ---------------- prep ----------------
__global__ void prep_kernel(const float* __restrict__ ref, const float* __restrict__ ws,
                            const float* __restrict__ wb, const float* __restrict__ cm) {
    int t = blockIdx.x * 256 + threadIdx.x;
    if (t < NN) {
        g_col[t * 3 + 0] = ref[t * 3 + 0] * 8.0f;
        g_col[t * 3 + 1] = ref[t * 3 + 1] * 8.0f;
        g_col[t * 3 + 2] = ref[t * 3 + 2] * 8.0f;
    }
    if (t < 64) {
        float d = (float)(t - 29);
        g_tap[t] = (t < 60) ? __expf(-0.5f * d * d / 9.0f) : 0.0f;  // theta_gamma = 3
    }
    if (t < CC * CC) {
        g_Ws[t] = cm[t] * ws[t % CC];
        g_Wb[t] = cm[t] * wb[t % CC];
    }
    // zero the haloed tmp planes once; interior is overwritten every iteration
    for (int i = t; i < CC * TMP_PLANE; i += 36 * 256) g_tmp2[i] = 0.0f;
}

// ---------------- build banded bilateral kernel (fp8, once) ----------------
// exp(-0.5*d2) rounds to e4m3 zero when d2 > 13.86; skipping expf there is exact.
__global__ void build_k_kernel() {
    int tile = blockIdx.y >> 3;
    int i0 = tile * RB + (blockIdx.y & 7) * 16;
    int jlo, jhi;
    tile_window(tile, jlo, jhi);
    int kcol = (blockIdx.x * 128 + threadIdx.x) * 4;
    int j0 = jlo + kcol;
    if (j0 >= jhi) return;                     // padding beyond window: never read
    float yj = (float)(j0 / WW), xj = (float)(j0 % WW);  // quad within one row (WW%4==0)
    float cr[4], cg[4], cb[4];
#pragma unroll
    for (int t = 0; t < 4; t++) {
        cr[t] = g_col[(j0 + t) * 3 + 0];
        cg[t] = g_col[(j0 + t) * 3 + 1];
        cb[t] = g_col[(j0 + t) * 3 + 2];
    }
    uint8_t* dst0 = g_Kb + (size_t)i0 * KB_W + kcol;
#pragma unroll 2
    for (int t = 0; t < 16; t++) {
        int i = i0 + t;
        float yi = (float)(i / WW), xi = (float)(i % WW);
        float ri = g_col[i * 3 + 0], gi = g_col[i * 3 + 1], bi = g_col[i * 3 + 2];
        float dy = yi - yj;
        float d2v[4];
        bool nearv = false;
#pragma unroll
        for (int s = 0; s < 4; s++) {
            float dx = xi - (xj + (float)s);
            float d2 = (dy * dy + dx * dx) * (1.0f / 64.0f);
            float dr = ri - cr[s], dg = gi - cg[s], db = bi - cb[s];
            d2 += dr * dr + dg * dg + db * db;
            d2v[s] = d2;
            nearv |= (d2 < 13.86f);
        }
        uint32_t packed = 0;
        if (__ballot_sync(0xffffffffu, nearv)) {   // whole warp far -> skip all MUFU
            if (nearv) {
#pragma unroll
                for (int s = 0; s < 4; s++) {
                    float e = (d2v[s] < 13.86f) ? __expf(-0.5f * d2v[s]) : 0.0f;
                    packed |= (uint32_t)to_e4m3(e) << (8 * s);
                }
            }
        }
        *reinterpret_cast<uint32_t*>(dst0 + (size_t)t * KB_W) = packed;
    }
}

// ---------------- prob emission (shared by softmax0 and update) ----------------
__device__ __forceinline__ void emit_probs(const float* v, int n) {
    float mx = -1e30f;
#pragma unroll
    for (int c = 0; c < CC; c++) mx = fmaxf(mx, v[c]);
    float s = 0.0f;
    float e[CC];
#pragma unroll
    for (int c = 0; c < CC; c++) { e[c] = __expf(v[c] - mx); s += e[c]; }
    float inv = 1.0f / s;
#pragma unroll
    for (int c = 0; c < CC; c++) {
        float p = e[c] * inv;
        g_pT[c * NN + n] = __float2half_rn(p);
        uint8_t hi = to_e4m3(p);
        float res = 64.0f * (p - from_e4m3(hi));
        g_pT8[c * NN + n] = hi;
        g_pT8[(CP + c) * NN + n] = to_e4m3(res);
    }
#pragma unroll
    for (int c = CC; c < CP; c++) {
        g_pT8[c * NN + n] = 0;
        g_pT8[(CP + c) * NN + n] = 0;
    }
}

__global__ void softmax0_kernel(const float* __restrict__ u) {
    int n = blockIdx.x * 128 + threadIdx.x;
    float v[CC];
#pragma unroll
    for (int c = 0; c < CC; c++) v[c] = u[n * CC + c];
    emit_probs(v, n);
}

// ---------------- separable spatial filtering: 60-tap Gaussian FIR ----------------
// G(d) < 2e-22 for |d| >= 30: dropped terms are below 1 ulp of the fp32 sums.
__global__ void conv_x_kernel() {   // grid = (96 y, 7 cg), block = 288 (3 ch * 96 x)
    __shared__ float sp[3][160];    // 29 zeros | 96 probs | 31 zeros
    __shared__ float tap[64];
    int tid = threadIdx.x;
    int sub = tid / 96, x = tid % 96;
    int y = blockIdx.x;
    int c = blockIdx.y * 3 + sub;
    if (tid < 64) tap[tid] = g_tap[tid];
    if (x < 29) sp[sub][x] = 0.0f;
    if (x >= 65) sp[sub][x + 60] = 0.0f;      // covers [125,156)
    sp[sub][x + 29] = __half2float(g_pT[c * NN + y * WW + x]);
    __syncthreads();
    float a0 = 0.f, a1 = 0.f, a2 = 0.f, a3 = 0.f;
#pragma unroll
    for (int t = 0; t < 60; t += 4) {
        a0 += tap[t + 0] * sp[sub][x + t + 0];
        a1 += tap[t + 1] * sp[sub][x + t + 1];
        a2 += tap[t + 2] * sp[sub][x + t + 2];
        a3 += tap[t + 3] * sp[sub][x + t + 3];
    }
    g_tmp2[c * TMP_PLANE + (y + 29) * WW + x] = (a0 + a1) + (a2 + a3);
}

__global__ void conv_y_kernel() {   // grid = (12 ytile, 21 c), block = 96 (x)
    __shared__ float tap[76];       // 8 zeros | 60 taps | 8 zeros
    int c = blockIdx.y, y0 = blockIdx.x * 8, x = threadIdx.x;
    if (x < 76) tap[x] = (x >= 8 && x < 68) ? g_tap[x - 8] : 0.0f;
    __syncthreads();
    float acc[8];
#pragma unroll
    for (int i = 0; i < 8; i++) acc[i] = 0.0f;
    // tmpPad image row (y0-29+s) lives at storage row (y0+s)
    const float* tp = g_tmp2 + c * TMP_PLANE + y0 * WW + x;
#pragma unroll
    for (int s = 0; s < 67; s++) {
        float v = tp[s * WW];
#pragma unroll
        for (int i = 0; i < 8; i++) acc[i] += tap[s - i + 8] * v;
    }
#pragma unroll
    for (int i = 0; i < 8; i++)
        g_S[c * NN + (y0 + i) * WW + x] = acc[i];
}

// ---------------- fp8 GEMM: banded, Bp = Kb @ pT8^T (hi & lo), m32 warp tiles ----------------
__device__ __forceinline__ void mma_fp8(float* d, uint32_t a0, uint32_t a1, uint32_t a2,
                                        uint32_t a3, uint32_t b0, uint32_t b1) {
    asm volatile(
        "mma.sync.aligned.m16n8k32.row.col.f32.e4m3.e4m3.f32 "
        "{%0,%1,%2,%3},{%4,%5,%6,%7},{%8,%9},{%0,%1,%2,%3};\n"
        : "+f"(d[0]), "+f"(d[1]), "+f"(d[2]), "+f"(d[3])
        : "r"(a0), "r"(a1), "r"(a2), "r"(a3), "r"(b0), "r"(b1));
}

__global__ void __launch_bounds__(128, 2) gemm_kernel() {
    // grid = (72, KSPLIT). Block: 128 rows; banded k-window split KSPLIT ways.
    __shared__ __align__(16) uint8_t sA[3 * SA_BUF];   // 49152 B
    __shared__ __align__(16) uint8_t sB[3 * SB_BUF];   // 18432 B
    int tid = threadIdx.x;
    int warp = tid >> 5, lane = tid & 31;
    int grp = lane >> 2, tig = lane & 3;
    int tile = blockIdx.x;
    int rowBase = tile * RB;

    int jlo, jhi;
    tile_window(tile, jlo, jhi);
    int len = jhi - jlo;
    int chunk = ((len / KSPLIT + KT - 1) / KT) * KT;
    int kstartRel = blockIdx.y * chunk;
    int kendRel = min(len, kstartRel + chunk);
    int NST = (kendRel > kstartRel) ? (kendRel - kstartRel) / KT : 0;

    const uint8_t* Arow0 = g_Kb + (size_t)rowBase * KB_W + kstartRel;
    const uint8_t* Bbase = g_pT8 + jlo + kstartRel;

    uint32_t sA_u = (uint32_t)__cvta_generic_to_shared(&sA[0]);
    uint32_t sB_u = (uint32_t)__cvta_generic_to_shared(&sB[0]);

    auto prefetch = [&](int s, int buf) {
        if (s >= NST) return;
        size_t kbase = (size_t)s * KT;
#pragma unroll
        for (int i = 0; i < 8; i++) {            // 1024 chunks of 16B for A (128 rows)
            int chunkid = tid + i * 128;
            int r = chunkid >> 3, c = chunkid & 7;
            const uint8_t* src = Arow0 + (size_t)r * KB_W + kbase + c * 16;
            uint32_t dst = sA_u + buf * SA_BUF + r * 128 + ((c ^ (r & 7)) << 4);
            CP_ASYNC16(dst, src);
        }
#pragma unroll
        for (int i = 0; i < 3; i++) {            // 384 chunks for B (48 rows)
            int chunkid = tid + i * 128;
            int r = chunkid >> 3, c = chunkid & 7;
            const uint8_t* src = Bbase + (size_t)r * NN + kbase + c * 16;
            uint32_t dst = sB_u + buf * SB_BUF + r * 128 + ((c ^ (r & 7)) << 4);
            CP_ASYNC16(dst, src);
        }
    };

    float d[2][6][4];
#pragma unroll
    for (int m = 0; m < 2; m++)
#pragma unroll
        for (int i = 0; i < 6; i++)
#pragma unroll
            for (int j = 0; j < 4; j++) d[m][i][j] = 0.0f;

    prefetch(0, 0); CP_COMMIT();
    prefetch(1, 1); CP_COMMIT();

    // ---- ldmatrix address setup (loop-invariant) ----
    int l7 = lane & 7;
    int aHalf = lane >> 4;
    int bHalf = (lane >> 3) & 1;
    uint32_t aBase[2];
#pragma unroll
    for (int m = 0; m < 2; m++) {
        int aRow = warp * 32 + m * 16 + ((lane >> 3) & 1) * 8 + l7;
        aBase[m] = sA_u + (uint32_t)aRow * 128;
    }
    uint32_t bBase[3];
#pragma unroll
    for (int p = 0; p < 3; p++)
        bBase[p] = sB_u + (uint32_t)(((2 * p + (lane >> 4)) * 8 + l7) * 128);
    int offA[4], offB[4];
#pragma unroll
    for (int kk = 0; kk < 4; kk++) {
        offA[kk] = (((2 * kk + aHalf) ^ l7) << 4);
        offB[kk] = (((2 * kk + bHalf) ^ l7) << 4);
    }

    int buf = 0;
    for (int s = 0; s < NST; s++) {
        CP_WAIT1();
        __syncthreads();
        prefetch(s + 2, (s + 2) % 3);
        CP_COMMIT();
        uint32_t A0 = aBase[0] + buf * SA_BUF;
        uint32_t A1 = aBase[1] + buf * SA_BUF;
        uint32_t B0 = bBase[0] + buf * SB_BUF;
        uint32_t B1 = bBase[1] + buf * SB_BUF;
        uint32_t B2 = bBase[2] + buf * SB_BUF;
        buf = (buf == 2) ? 0 : buf + 1;
#pragma unroll
        for (int kk = 0; kk < 4; kk++) {
            uint32_t a00, a01, a02, a03, a10, a11, a12, a13;
            LDSM4(a00, a01, a02, a03, A0 + offA[kk]);
            LDSM4(a10, a11, a12, a13, A1 + offA[kk]);
            uint32_t b00, b01, b10, b11;
            LDSM4(b00, b01, b10, b11, B0 + offB[kk]);
            uint32_t b20, b21, b30, b31;
            LDSM4(b20, b21, b30, b31, B1 + offB[kk]);
            uint32_t b40, b41, b50, b51;
            LDSM4(b40, b41, b50, b51, B2 + offB[kk]);
            mma_fp8(d[0][0], a00, a01, a02, a03, b00, b01);
            mma_fp8(d[0][1], a00, a01, a02, a03, b10, b11);
            mma_fp8(d[0][2], a00, a01, a02, a03, b20, b21);
            mma_fp8(d[0][3], a00, a01, a02, a03, b30, b31);
            mma_fp8(d[0][4], a00, a01, a02, a03, b40, b41);
            mma_fp8(d[0][5], a00, a01, a02, a03, b50, b51);
            mma_fp8(d[1][0], a10, a11, a12, a13, b00, b01);
            mma_fp8(d[1][1], a10, a11, a12, a13, b10, b11);
            mma_fp8(d[1][2], a10, a11, a12, a13, b20, b21);
            mma_fp8(d[1][3], a10, a11, a12, a13, b30, b31);
            mma_fp8(d[1][4], a10, a11, a12, a13, b40, b41);
            mma_fp8(d[1][5], a10, a11, a12, a13, b50, b51);
        }
    }

    float* outp = g_Bp[blockIdx.y];
#pragma unroll
    for (int m = 0; m < 2; m++) {
        int row0 = rowBase + warp * 32 + m * 16 + grp;
#pragma unroll
        for (int nt = 0; nt < 3; nt++) {   // combine hi + lo/64
            int col = nt * 8 + 2 * tig;
            float v00 = d[m][nt][0] + d[m][nt + 3][0] * (1.0f / 64.0f);
            float v01 = d[m][nt][1] + d[m][nt + 3][1] * (1.0f / 64.0f);
            float v10 = d[m][nt][2] + d[m][nt + 3][2] * (1.0f / 64.0f);
            float v11 = d[m][nt][3] + d[m][nt + 3][3] * (1.0f / 64.0f);
            *reinterpret_cast<float2*>(&outp[(size_t)row0 * CP + col]) = make_float2(v00, v01);
            *reinterpret_cast<float2*>(&outp[(size_t)(row0 + 8) * CP + col]) = make_float2(v10, v11);
        }
    }
}

// ---------------- fused update + softmax: q = u - S@Ws^T - B@Wb^T, then probs ----------------
__global__ void update_kernel(const float* __restrict__ u, float* __restrict__ outp, int last) {
    __shared__ float su[128 * CC];
    __shared__ float sws[CC * CC], swb[CC * CC];
    int tid = threadIdx.x;
    for (int t = tid; t < CC * CC; t += 128) { sws[t] = g_Ws[t]; swb[t] = g_Wb[t]; }
    int base = blockIdx.x * 128 * CC;
    for (int t = tid; t < 128 * CC; t += 128) su[t] = u[base + t];
    __syncthreads();
    int n = blockIdx.x * 128 + tid;

    float sv[CC], bv[CP];
#pragma unroll
    for (int c = 0; c < CC; c++) sv[c] = g_S[c * NN + n];
#pragma unroll
    for (int q4 = 0; q4 < 6; q4++) {
        float4 a = *reinterpret_cast<const float4*>(&g_Bp[0][(size_t)n * CP + q4 * 4]);
        float4 b = *reinterpret_cast<const float4*>(&g_Bp[1][(size_t)n * CP + q4 * 4]);
        float4 cc4 = *reinterpret_cast<const float4*>(&g_Bp[2][(size_t)n * CP + q4 * 4]);
        float4 e = *reinterpret_cast<const float4*>(&g_Bp[3][(size_t)n * CP + q4 * 4]);
        bv[q4 * 4 + 0] = a.x + b.x + cc4.x + e.x;
        bv[q4 * 4 + 1] = a.y + b.y + cc4.y + e.y;
        bv[q4 * 4 + 2] = a.z + b.z + cc4.z + e.z;
        bv[q4 * 4 + 3] = a.w + b.w + cc4.w + e.w;
    }

    float qn[CC];
#pragma unroll
    for (int k = 0; k < CC; k++) {
        float acc = 0.0f;
#pragma unroll
        for (int c = 0; c < CC; c++)
            acc += sws[k * CC + c] * sv[c] + swb[k * CC + c] * bv[c];
        qn[k] = su[tid * CC + k] - acc;
    }

    if (last) {
#pragma unroll
        for (int k = 0; k < CC; k++) outp[n * CC + k] = qn[k];
    } else {
        emit_probs(qn, n);
    }
}

// ---------------- launch: fork-join DAG (convs overlap gemm; softmax0+convs overlap build_k) --
extern "C" void kernel_launch(void* const* d_in, const int* in_sizes, int n_in,
                              void* d_out, int out_size) {
    const float* u   = (const float*)d_in[0];
    const float* ref = (const float*)d_in[1];
    const float* ws  = (const float*)d_in[2];
    const float* wb  = (const float*)d_in[3];
    const float* cm  = (const float*)d_in[4];
    float* out = (float*)d_out;

    static cudaStream_t s2 = nullptr;
    static cudaEvent_t eFork = nullptr, eEmit = nullptr, eConv = nullptr;
    if (s2 == nullptr) {
        cudaStreamCreateWithFlags(&s2, cudaStreamNonBlocking);
        cudaEventCreateWithFlags(&eFork, cudaEventDisableTiming);
        cudaEventCreateWithFlags(&eEmit, cudaEventDisableTiming);
        cudaEventCreateWithFlags(&eConv, cudaEventDisableTiming);
    }

    // fork side stream off the main (legacy) stream
    cudaEventRecord(eFork, 0);
    cudaStreamWaitEvent(s2, eFork, 0);

    // main: prep -> build_K (long). side: softmax0 -> convs (independent of K).
    prep_kernel<<<36, 256>>>(ref, ws, wb, cm);
    build_k_kernel<<<dim3(13, 576), 128>>>();

    softmax0_kernel<<<72, 128, 0, s2>>>(u);
    cudaEventRecord(eEmit, s2);      // probs ready (iteration 0)

    for (int it = 0; it < 5; it++) {
        if (it > 0) cudaStreamWaitEvent(s2, eEmit, 0);
        conv_x_kernel<<<dim3(96, 7), 288, 0, s2>>>();
        conv_y_kernel<<<dim3(12, 21), 96, 0, s2>>>();
        cudaEventRecord(eConv, s2);

        if (it == 0) cudaStreamWaitEvent(0, eEmit, 0);  // gemm needs softmax0
        gemm_kernel<<<dim3(NTILES, KSPLIT), 128>>>();

        cudaStreamWaitEvent(0, eConv, 0);                // update needs convs
        update_kernel<<<72, 128>>>(u, out, it == 4 ? 1 : 0);
        if (it < 4) cudaEventRecord(eEmit, 0);           // new probs for next iter
    }
}